// round 6
// baseline (speedup 1.0000x reference)
#include <cuda_runtime.h>
#include <cuda_fp16.h>

// Problem constants (match reference setup_inputs)
#define N_NODES 25000
#define N_EDGES 400000
#define F_DIM   128
#define S_DIM   256
#define L_DIM   64
#define ROUNDS  4

// ---------------- scratch (static __device__, no allocations) ----------------
__device__ float  g_state[N_NODES * S_DIM];                 // fp32 master
__device__ __half g_state_h[N_NODES * S_DIM];               // fp16 GEMM operand
__device__ __half g_xh[N_NODES * F_DIM];
__device__ __half g_Psrc[N_NODES * S_DIM];
__device__ float  g_Pdst[N_NODES * S_DIM];
__device__ __half g_WinT[S_DIM * F_DIM];                    // [N=256][K=128]
__device__ __half g_WcatT[ROUNDS * 2 * S_DIM * S_DIM];      // [r][N=512][K=256]
__device__ __half g_WoutT[L_DIM * S_DIM];                   // [N=64][K=256]
__device__ int    g_cnt[N_NODES];
__device__ int    g_cur[N_NODES];
__device__ int    g_rowptr[N_NODES + 1];
__device__ int    g_esrc[N_EDGES];

// ---------------- CSR build (counting sort by dest) ----------------
__global__ void zero_counts_kernel() {
    int i = blockIdx.x * blockDim.x + threadIdx.x;
    if (i < N_NODES) { g_cnt[i] = 0; g_cur[i] = 0; }
}

__global__ void hist_kernel(const int* __restrict__ edge_index) {
    int e = blockIdx.x * blockDim.x + threadIdx.x;
    if (e < N_EDGES) {
        int d = __ldg(&edge_index[N_EDGES + e]);
        atomicAdd(&g_cnt[d], 1);
    }
}

__global__ void scan_kernel() {
    __shared__ int warp_tot[32];
    const int CH = (N_NODES + 1023) / 1024;   // 25
    int t = threadIdx.x;
    int lane = t & 31, wid = t >> 5;
    int base = t * CH;
    int sum = 0;
#pragma unroll
    for (int i = 0; i < CH; i++) {
        int idx = base + i;
        if (idx < N_NODES) sum += g_cnt[idx];
    }
    int v = sum;
#pragma unroll
    for (int off = 1; off < 32; off <<= 1) {
        int n = __shfl_up_sync(0xffffffff, v, off);
        if (lane >= off) v += n;
    }
    if (lane == 31) warp_tot[wid] = v;
    __syncthreads();
    if (wid == 0) {
        int w = warp_tot[lane];
#pragma unroll
        for (int off = 1; off < 32; off <<= 1) {
            int n = __shfl_up_sync(0xffffffff, w, off);
            if (lane >= off) w += n;
        }
        warp_tot[lane] = w;
    }
    __syncthreads();
    int excl = v - sum + (wid > 0 ? warp_tot[wid - 1] : 0);
    int run = excl;
#pragma unroll
    for (int i = 0; i < CH; i++) {
        int idx = base + i;
        if (idx < N_NODES) { g_rowptr[idx] = run; run += g_cnt[idx]; }
    }
    if (t == 1023) g_rowptr[N_NODES] = run;
}

__global__ void fill_kernel(const int* __restrict__ edge_index) {
    int e = blockIdx.x * blockDim.x + threadIdx.x;
    if (e < N_EDGES) {
        int s = __ldg(&edge_index[e]);
        int d = __ldg(&edge_index[N_EDGES + e]);
        int pos = g_rowptr[d] + atomicAdd(&g_cur[d], 1);
        g_esrc[pos] = s;
    }
}

// ---------------- fp16 operand prep (x + all weights in one launch) ----------------
__global__ void prep_kernel(const float* __restrict__ x,
                            const float* __restrict__ W_in,
                            const float* __restrict__ W_msg,
                            const float* __restrict__ W_out) {
    const int NX = N_NODES * F_DIM;
    const int N1 = S_DIM * F_DIM;
    const int N2 = ROUNDS * 2 * S_DIM * S_DIM;
    const int N3 = L_DIM * S_DIM;
    int i = blockIdx.x * blockDim.x + threadIdx.x;
    if (i < NX) {
        g_xh[i] = __float2half(x[i]);
    } else if (i < NX + N1) {
        int t = i - NX;
        int j = t / F_DIM, k = t % F_DIM;
        g_WinT[t] = __float2half(W_in[k * S_DIM + j]);
    } else if (i < NX + N1 + N2) {
        int t = i - NX - N1;
        int r = t / (2 * S_DIM * S_DIM);
        int rem = t % (2 * S_DIM * S_DIM);
        int j = rem / S_DIM;       // 0..511
        int k = rem % S_DIM;
        const float* Wr = W_msg + (size_t)r * 2 * S_DIM * S_DIM;
        float v = (j < S_DIM) ? Wr[k * S_DIM + j] : Wr[(S_DIM + k) * S_DIM + (j - S_DIM)];
        g_WcatT[t] = __float2half(v);
    } else if (i < NX + N1 + N2 + N3) {
        int t = i - NX - N1 - N2;
        int j = t / S_DIM, k = t % S_DIM;
        g_WoutT[t] = __float2half(W_out[k * L_DIM + j]);
    }
}

// ---------------- fp16 tensor-core GEMM, double-buffered ----------------
// C[M,N] = act(A[M,K] @ B^T + bias), B given as [N][K] fp16 (pre-transposed).
// BM=128, BN=128, BK=32, 256 threads (8 warps), warp tile 64x32 via m16n8k16.
#define TBM 128
#define TBN 128
#define TBK 32
#define KP  56
#define TILE_ELEMS (128 * KP)
#define SMEM_BYTES (4 * TILE_ELEMS * 2)

__global__ __launch_bounds__(256, 2) void gemm_f16_kernel(
    const __half* __restrict__ A, const __half* __restrict__ B,
    const float* __restrict__ bias, float* __restrict__ C,
    __half* __restrict__ Ch, __half* __restrict__ Csrc, float* __restrict__ Cdst,
    int M, int N, int K, int do_relu)
{
    extern __shared__ __half sm[];
    __half* As = sm;                     // [2][128][KP]
    __half* Bs = sm + 2 * TILE_ELEMS;    // [2][128][KP]

    int tid  = threadIdx.x;
    int lane = tid & 31;
    int wid  = tid >> 5;
    int warp_m = wid & 1;
    int warp_n = wid >> 1;
    int m_warp = warp_m * 64;
    int n_warp = warp_n * 32;
    int g   = lane >> 2;
    int tig = lane & 3;

    int row_blk = blockIdx.y * TBM;
    int col_blk = blockIdx.x * TBN;

    float c[4][4][4];
#pragma unroll
    for (int mt = 0; mt < 4; mt++)
#pragma unroll
        for (int nt = 0; nt < 4; nt++)
#pragma unroll
            for (int i = 0; i < 4; i++) c[mt][nt][i] = 0.f;

    int kt  = tid & 3;
    int trow = tid >> 2;

    int nk = K / TBK;
    uint4 av[2], bv[2];
    const uint4 zero4 = make_uint4(0, 0, 0, 0);

#pragma unroll
    for (int p = 0; p < 2; p++) {
        int ar = row_blk + p * 64 + trow;
        av[p] = (ar < M) ? *(const uint4*)&A[(size_t)ar * K + kt * 8] : zero4;
        int br = col_blk + p * 64 + trow;
        bv[p] = (br < N) ? *(const uint4*)&B[(size_t)br * K + kt * 8] : zero4;
    }

    for (int t = 0; t < nk; t++) {
        int cur = t & 1;
        __half* Ac = As + cur * TILE_ELEMS;
        __half* Bc = Bs + cur * TILE_ELEMS;

#pragma unroll
        for (int p = 0; p < 2; p++) {
            int row = p * 64 + trow;
            *(uint4*)&Ac[row * KP + kt * 8] = av[p];
            *(uint4*)&Bc[row * KP + kt * 8] = bv[p];
        }
        __syncthreads();

        if (t + 1 < nk) {
            int k0 = (t + 1) * TBK;
#pragma unroll
            for (int p = 0; p < 2; p++) {
                int ar = row_blk + p * 64 + trow;
                av[p] = (ar < M) ? *(const uint4*)&A[(size_t)ar * K + k0 + kt * 8] : zero4;
                int br = col_blk + p * 64 + trow;
                bv[p] = (br < N) ? *(const uint4*)&B[(size_t)br * K + k0 + kt * 8] : zero4;
            }
        }

#pragma unroll
        for (int ks = 0; ks < TBK; ks += 16) {
            unsigned af[4][4], bf[4][2];
#pragma unroll
            for (int mt = 0; mt < 4; mt++) {
                int mb = m_warp + mt * 16;
                af[mt][0] = *(unsigned*)&Ac[(mb + g) * KP + ks + tig * 2];
                af[mt][1] = *(unsigned*)&Ac[(mb + g + 8) * KP + ks + tig * 2];
                af[mt][2] = *(unsigned*)&Ac[(mb + g) * KP + ks + tig * 2 + 8];
                af[mt][3] = *(unsigned*)&Ac[(mb + g + 8) * KP + ks + tig * 2 + 8];
            }
#pragma unroll
            for (int nt = 0; nt < 4; nt++) {
                int nb = n_warp + nt * 8;
                bf[nt][0] = *(unsigned*)&Bc[(nb + g) * KP + ks + tig * 2];
                bf[nt][1] = *(unsigned*)&Bc[(nb + g) * KP + ks + tig * 2 + 8];
            }
#pragma unroll
            for (int mt = 0; mt < 4; mt++)
#pragma unroll
                for (int nt = 0; nt < 4; nt++) {
                    asm volatile(
                        "mma.sync.aligned.m16n8k16.row.col.f32.f16.f16.f32 "
                        "{%0,%1,%2,%3}, {%4,%5,%6,%7}, {%8,%9}, {%0,%1,%2,%3};"
                        : "+f"(c[mt][nt][0]), "+f"(c[mt][nt][1]),
                          "+f"(c[mt][nt][2]), "+f"(c[mt][nt][3])
                        : "r"(af[mt][0]), "r"(af[mt][1]), "r"(af[mt][2]), "r"(af[mt][3]),
                          "r"(bf[nt][0]), "r"(bf[nt][1]));
                }
        }
        __syncthreads();
    }

#pragma unroll
    for (int mt = 0; mt < 4; mt++) {
#pragma unroll
        for (int nt = 0; nt < 4; nt++) {
            int col = col_blk + n_warp + nt * 8 + tig * 2;
            if (col >= N) continue;
            float bv0 = bias ? bias[col] : 0.f;
            float bv1 = bias ? bias[col + 1] : 0.f;
            int r0 = row_blk + m_warp + mt * 16 + g;
            int r1 = r0 + 8;
            float2 o0, o1;
            o0.x = c[mt][nt][0] + bv0; o0.y = c[mt][nt][1] + bv1;
            o1.x = c[mt][nt][2] + bv0; o1.y = c[mt][nt][3] + bv1;
            if (do_relu) {
                o0.x = fmaxf(o0.x, 0.f); o0.y = fmaxf(o0.y, 0.f);
                o1.x = fmaxf(o1.x, 0.f); o1.y = fmaxf(o1.y, 0.f);
            }
            if (Csrc) {
                if (col < S_DIM) {
                    __half2* H = (__half2*)Csrc;
                    if (r0 < M) H[((size_t)r0 * S_DIM + col) >> 1] = __floats2half2_rn(o0.x, o0.y);
                    if (r1 < M) H[((size_t)r1 * S_DIM + col) >> 1] = __floats2half2_rn(o1.x, o1.y);
                } else {
                    int cc = col - S_DIM;
                    if (r0 < M) *(float2*)&Cdst[(size_t)r0 * S_DIM + cc] = o0;
                    if (r1 < M) *(float2*)&Cdst[(size_t)r1 * S_DIM + cc] = o1;
                }
            } else {
                if (r0 < M) {
                    *(float2*)&C[(size_t)r0 * N + col] = o0;
                    if (Ch) *(__half2*)&Ch[(size_t)r0 * N + col] = __floats2half2_rn(o0.x, o0.y);
                }
                if (r1 < M) {
                    *(float2*)&C[(size_t)r1 * N + col] = o1;
                    if (Ch) *(__half2*)&Ch[(size_t)r1 * N + col] = __floats2half2_rn(o1.x, o1.y);
                }
            }
        }
    }
}

// ---------------- per-node aggregation: TWO warps per node, column split ----------------
// Each warp owns 128 columns (lane -> 4 cols, uint2 gather = 8B/lane).
// state[n] += sum_e relu(h2f(Psrc[src_e]) + Pdst[n] + b); writes fp32 + fp16 state.
__global__ __launch_bounds__(256) void aggregate_kernel(const float* __restrict__ b_msg_r) {
    int gw = blockIdx.x * 8 + (threadIdx.x >> 5);   // global warp id
    int node = gw >> 1;
    if (node >= N_NODES) return;
    int half = gw & 1;
    int lane = threadIdx.x & 31;
    int col = half * 128 + lane * 4;                // 4 fp32 / 4 fp16 columns per lane

    // base = Pdst[node][col..col+3] + b[col..col+3]
    float4 base = *(const float4*)&g_Pdst[(size_t)node * S_DIM + col];
    float4 bb   = *(const float4*)&b_msg_r[col];
    base.x += bb.x; base.y += bb.y; base.z += bb.z; base.w += bb.w;

    float4 acc = make_float4(0.f, 0.f, 0.f, 0.f);

    const __half* Ph = g_Psrc;
    int s = g_rowptr[node];
    int e = g_rowptr[node + 1];

#define ACC_EDGE(q)                                                \
    do {                                                           \
        float2 f0 = __half22float2(*(__half2*)&(q).x);             \
        float2 f1 = __half22float2(*(__half2*)&(q).y);             \
        acc.x += fmaxf(f0.x + base.x, 0.f);                        \
        acc.y += fmaxf(f0.y + base.y, 0.f);                        \
        acc.z += fmaxf(f1.x + base.z, 0.f);                        \
        acc.w += fmaxf(f1.y + base.w, 0.f);                        \
    } while (0)

    int i = s;
    for (; i + 4 <= e; i += 4) {
        int s0 = __ldg(&g_esrc[i]);
        int s1 = __ldg(&g_esrc[i + 1]);
        int s2 = __ldg(&g_esrc[i + 2]);
        int s3 = __ldg(&g_esrc[i + 3]);
        uint2 q0 = *(const uint2*)&Ph[(size_t)s0 * S_DIM + col];
        uint2 q1 = *(const uint2*)&Ph[(size_t)s1 * S_DIM + col];
        uint2 q2 = *(const uint2*)&Ph[(size_t)s2 * S_DIM + col];
        uint2 q3 = *(const uint2*)&Ph[(size_t)s3 * S_DIM + col];
        ACC_EDGE(q0); ACC_EDGE(q1); ACC_EDGE(q2); ACC_EDGE(q3);
    }
    for (; i < e; i++) {
        int s0 = __ldg(&g_esrc[i]);
        uint2 q0 = *(const uint2*)&Ph[(size_t)s0 * S_DIM + col];
        ACC_EDGE(q0);
    }
#undef ACC_EDGE

    float4* st = (float4*)&g_state[(size_t)node * S_DIM + col];
    float4 sv = *st;
    sv.x += acc.x; sv.y += acc.y; sv.z += acc.z; sv.w += acc.w;
    *st = sv;

    // fp16 shadow for the next GEMM
    __half2 h0 = __floats2half2_rn(sv.x, sv.y);
    __half2 h1 = __floats2half2_rn(sv.z, sv.w);
    uint2 pk;
    pk.x = *(unsigned*)&h0; pk.y = *(unsigned*)&h1;
    *(uint2*)&g_state_h[(size_t)node * S_DIM + col] = pk;
}

// ---------------- launch ----------------
extern "C" void kernel_launch(void* const* d_in, const int* in_sizes, int n_in,
                              void* d_out, int out_size)
{
    const float* x        = (const float*)d_in[0];
    const int*   eidx     = (const int*)d_in[1];
    // d_in[2] = batch (unused by reference)
    const float* W_in     = (const float*)d_in[3];
    const float* b_in     = (const float*)d_in[4];
    const float* W_msg    = (const float*)d_in[5];   // [ROUNDS, 2S, S]
    const float* b_msg    = (const float*)d_in[6];   // [ROUNDS, S]
    const float* W_out    = (const float*)d_in[7];
    const float* b_out    = (const float*)d_in[8];
    float*       out      = (float*)d_out;

    float*  state;   cudaGetSymbolAddress((void**)&state,   g_state);
    __half* state_h; cudaGetSymbolAddress((void**)&state_h, g_state_h);
    __half* xh;      cudaGetSymbolAddress((void**)&xh,      g_xh);
    __half* Psrc;    cudaGetSymbolAddress((void**)&Psrc,    g_Psrc);
    float*  Pdst;    cudaGetSymbolAddress((void**)&Pdst,    g_Pdst);
    __half* WinT;    cudaGetSymbolAddress((void**)&WinT,    g_WinT);
    __half* WcatT;   cudaGetSymbolAddress((void**)&WcatT,   g_WcatT);
    __half* WoutT;   cudaGetSymbolAddress((void**)&WoutT,   g_WoutT);

    cudaFuncSetAttribute(gemm_f16_kernel,
                         cudaFuncAttributeMaxDynamicSharedMemorySize, SMEM_BYTES);

    // 1) CSR build + fp16 operand prep
    zero_counts_kernel<<<(N_NODES + 255) / 256, 256>>>();
    hist_kernel<<<(N_EDGES + 255) / 256, 256>>>(eidx);
    scan_kernel<<<1, 1024>>>();
    fill_kernel<<<(N_EDGES + 255) / 256, 256>>>(eidx);
    {
        int tot = N_NODES * F_DIM + S_DIM * F_DIM
                + ROUNDS * 2 * S_DIM * S_DIM + L_DIM * S_DIM;
        prep_kernel<<<(tot + 255) / 256, 256>>>(x, W_in, W_msg, W_out);
    }

    // 2) input net: state = relu(x @ W_in + b_in), also fp16 shadow
    {
        dim3 grid(S_DIM / TBN, (N_NODES + TBM - 1) / TBM);
        gemm_f16_kernel<<<grid, 256, SMEM_BYTES>>>(
            xh, WinT, b_in, state, state_h, nullptr, nullptr,
            N_NODES, S_DIM, F_DIM, 1);
    }

    // 3) message rounds
    for (int r = 0; r < ROUNDS; r++) {
        {
            dim3 grid((2 * S_DIM) / TBN, (N_NODES + TBM - 1) / TBM);
            gemm_f16_kernel<<<grid, 256, SMEM_BYTES>>>(
                state_h, WcatT + (size_t)r * 2 * S_DIM * S_DIM, nullptr, nullptr,
                nullptr, Psrc, Pdst, N_NODES, 2 * S_DIM, S_DIM, 0);
        }
        aggregate_kernel<<<(2 * N_NODES + 7) / 8, 256>>>(b_msg + (size_t)r * S_DIM);
    }

    // 4) output net: out = state @ W_out + b_out
    {
        dim3 grid(1, (N_NODES + TBM - 1) / TBM);
        gemm_f16_kernel<<<grid, 256, SMEM_BYTES>>>(
            state_h, WoutT, b_out, out, nullptr, nullptr, nullptr,
            N_NODES, L_DIM, S_DIM, 0);
    }
}

// round 7
// speedup vs baseline: 1.0662x; 1.0662x over previous
#include <cuda_runtime.h>
#include <cuda_fp16.h>

// Problem constants (match reference setup_inputs)
#define N_NODES 25000
#define N_EDGES 400000
#define F_DIM   128
#define S_DIM   256
#define L_DIM   64
#define ROUNDS  4

// ---------------- scratch (static __device__, no allocations) ----------------
__device__ float  g_state[N_NODES * S_DIM];                 // fp32 master
__device__ __half g_state_h[N_NODES * S_DIM];               // fp16 GEMM operand
__device__ __half g_xh[N_NODES * F_DIM];
__device__ __half g_Psrc[N_NODES * S_DIM];                  // fp16 src-half of P
__device__ __half g_Pdst[N_NODES * S_DIM];                  // fp16 dst-half of P
__device__ __half g_WinT[S_DIM * F_DIM];                    // [N=256][K=128]
__device__ __half g_WcatT[ROUNDS * 2 * S_DIM * S_DIM];      // [r][N=512][K=256]
__device__ __half g_WoutT[L_DIM * S_DIM];                   // [N=64][K=256]
__device__ int    g_cnt[N_NODES];
__device__ int    g_cur[N_NODES];
__device__ int    g_rowptr[N_NODES + 1];
__device__ int    g_esrc[N_EDGES];

// ---------------- CSR build (counting sort by dest) ----------------
__global__ void zero_counts_kernel() {
    int i = blockIdx.x * blockDim.x + threadIdx.x;
    if (i < N_NODES) { g_cnt[i] = 0; g_cur[i] = 0; }
}

__global__ void hist_kernel(const int* __restrict__ edge_index) {
    int e = blockIdx.x * blockDim.x + threadIdx.x;
    if (e < N_EDGES) {
        int d = __ldg(&edge_index[N_EDGES + e]);
        atomicAdd(&g_cnt[d], 1);
    }
}

__global__ void scan_kernel() {
    __shared__ int warp_tot[32];
    const int CH = (N_NODES + 1023) / 1024;   // 25
    int t = threadIdx.x;
    int lane = t & 31, wid = t >> 5;
    int base = t * CH;
    int sum = 0;
#pragma unroll
    for (int i = 0; i < CH; i++) {
        int idx = base + i;
        if (idx < N_NODES) sum += g_cnt[idx];
    }
    int v = sum;
#pragma unroll
    for (int off = 1; off < 32; off <<= 1) {
        int n = __shfl_up_sync(0xffffffff, v, off);
        if (lane >= off) v += n;
    }
    if (lane == 31) warp_tot[wid] = v;
    __syncthreads();
    if (wid == 0) {
        int w = warp_tot[lane];
#pragma unroll
        for (int off = 1; off < 32; off <<= 1) {
            int n = __shfl_up_sync(0xffffffff, w, off);
            if (lane >= off) w += n;
        }
        warp_tot[lane] = w;
    }
    __syncthreads();
    int excl = v - sum + (wid > 0 ? warp_tot[wid - 1] : 0);
    int run = excl;
#pragma unroll
    for (int i = 0; i < CH; i++) {
        int idx = base + i;
        if (idx < N_NODES) { g_rowptr[idx] = run; run += g_cnt[idx]; }
    }
    if (t == 1023) g_rowptr[N_NODES] = run;
}

__global__ void fill_kernel(const int* __restrict__ edge_index) {
    int e = blockIdx.x * blockDim.x + threadIdx.x;
    if (e < N_EDGES) {
        int s = __ldg(&edge_index[e]);
        int d = __ldg(&edge_index[N_EDGES + e]);
        int pos = g_rowptr[d] + atomicAdd(&g_cur[d], 1);
        g_esrc[pos] = s;
    }
}

// ---------------- fp16 operand prep (x + all weights in one launch) ----------------
__global__ void prep_kernel(const float* __restrict__ x,
                            const float* __restrict__ W_in,
                            const float* __restrict__ W_msg,
                            const float* __restrict__ W_out) {
    const int NX = N_NODES * F_DIM;
    const int N1 = S_DIM * F_DIM;
    const int N2 = ROUNDS * 2 * S_DIM * S_DIM;
    const int N3 = L_DIM * S_DIM;
    int i = blockIdx.x * blockDim.x + threadIdx.x;
    if (i < NX) {
        g_xh[i] = __float2half(x[i]);
    } else if (i < NX + N1) {
        int t = i - NX;
        int j = t / F_DIM, k = t % F_DIM;
        g_WinT[t] = __float2half(W_in[k * S_DIM + j]);
    } else if (i < NX + N1 + N2) {
        int t = i - NX - N1;
        int r = t / (2 * S_DIM * S_DIM);
        int rem = t % (2 * S_DIM * S_DIM);
        int j = rem / S_DIM;       // 0..511
        int k = rem % S_DIM;
        const float* Wr = W_msg + (size_t)r * 2 * S_DIM * S_DIM;
        float v = (j < S_DIM) ? Wr[k * S_DIM + j] : Wr[(S_DIM + k) * S_DIM + (j - S_DIM)];
        g_WcatT[t] = __float2half(v);
    } else if (i < NX + N1 + N2 + N3) {
        int t = i - NX - N1 - N2;
        int j = t / S_DIM, k = t % S_DIM;
        g_WoutT[t] = __float2half(W_out[k * L_DIM + j]);
    }
}

// ---------------- fp16 tensor-core GEMM, double-buffered ----------------
// C[M,N] = act(A[M,K] @ B^T + bias), B given as [N][K] fp16 (pre-transposed).
// BM=128, BN=128, BK=32, 256 threads (8 warps), warp tile 64x32 via m16n8k16.
#define TBM 128
#define TBN 128
#define TBK 32
#define KP  56
#define TILE_ELEMS (128 * KP)
#define SMEM_BYTES (4 * TILE_ELEMS * 2)

__global__ __launch_bounds__(256, 2) void gemm_f16_kernel(
    const __half* __restrict__ A, const __half* __restrict__ B,
    const float* __restrict__ bias, float* __restrict__ C,
    __half* __restrict__ Ch, __half* __restrict__ Csrc, __half* __restrict__ Cdst,
    int M, int N, int K, int do_relu)
{
    extern __shared__ __half sm[];
    __half* As = sm;                     // [2][128][KP]
    __half* Bs = sm + 2 * TILE_ELEMS;    // [2][128][KP]

    int tid  = threadIdx.x;
    int lane = tid & 31;
    int wid  = tid >> 5;
    int warp_m = wid & 1;
    int warp_n = wid >> 1;
    int m_warp = warp_m * 64;
    int n_warp = warp_n * 32;
    int g   = lane >> 2;
    int tig = lane & 3;

    int row_blk = blockIdx.y * TBM;
    int col_blk = blockIdx.x * TBN;

    float c[4][4][4];
#pragma unroll
    for (int mt = 0; mt < 4; mt++)
#pragma unroll
        for (int nt = 0; nt < 4; nt++)
#pragma unroll
            for (int i = 0; i < 4; i++) c[mt][nt][i] = 0.f;

    int kt  = tid & 3;
    int trow = tid >> 2;

    int nk = K / TBK;
    uint4 av[2], bv[2];
    const uint4 zero4 = make_uint4(0, 0, 0, 0);

#pragma unroll
    for (int p = 0; p < 2; p++) {
        int ar = row_blk + p * 64 + trow;
        av[p] = (ar < M) ? *(const uint4*)&A[(size_t)ar * K + kt * 8] : zero4;
        int br = col_blk + p * 64 + trow;
        bv[p] = (br < N) ? *(const uint4*)&B[(size_t)br * K + kt * 8] : zero4;
    }

    for (int t = 0; t < nk; t++) {
        int cur = t & 1;
        __half* Ac = As + cur * TILE_ELEMS;
        __half* Bc = Bs + cur * TILE_ELEMS;

#pragma unroll
        for (int p = 0; p < 2; p++) {
            int row = p * 64 + trow;
            *(uint4*)&Ac[row * KP + kt * 8] = av[p];
            *(uint4*)&Bc[row * KP + kt * 8] = bv[p];
        }
        __syncthreads();

        if (t + 1 < nk) {
            int k0 = (t + 1) * TBK;
#pragma unroll
            for (int p = 0; p < 2; p++) {
                int ar = row_blk + p * 64 + trow;
                av[p] = (ar < M) ? *(const uint4*)&A[(size_t)ar * K + k0 + kt * 8] : zero4;
                int br = col_blk + p * 64 + trow;
                bv[p] = (br < N) ? *(const uint4*)&B[(size_t)br * K + k0 + kt * 8] : zero4;
            }
        }

#pragma unroll
        for (int ks = 0; ks < TBK; ks += 16) {
            unsigned af[4][4], bf[4][2];
#pragma unroll
            for (int mt = 0; mt < 4; mt++) {
                int mb = m_warp + mt * 16;
                af[mt][0] = *(unsigned*)&Ac[(mb + g) * KP + ks + tig * 2];
                af[mt][1] = *(unsigned*)&Ac[(mb + g + 8) * KP + ks + tig * 2];
                af[mt][2] = *(unsigned*)&Ac[(mb + g) * KP + ks + tig * 2 + 8];
                af[mt][3] = *(unsigned*)&Ac[(mb + g + 8) * KP + ks + tig * 2 + 8];
            }
#pragma unroll
            for (int nt = 0; nt < 4; nt++) {
                int nb = n_warp + nt * 8;
                bf[nt][0] = *(unsigned*)&Bc[(nb + g) * KP + ks + tig * 2];
                bf[nt][1] = *(unsigned*)&Bc[(nb + g) * KP + ks + tig * 2 + 8];
            }
#pragma unroll
            for (int mt = 0; mt < 4; mt++)
#pragma unroll
                for (int nt = 0; nt < 4; nt++) {
                    asm volatile(
                        "mma.sync.aligned.m16n8k16.row.col.f32.f16.f16.f32 "
                        "{%0,%1,%2,%3}, {%4,%5,%6,%7}, {%8,%9}, {%0,%1,%2,%3};"
                        : "+f"(c[mt][nt][0]), "+f"(c[mt][nt][1]),
                          "+f"(c[mt][nt][2]), "+f"(c[mt][nt][3])
                        : "r"(af[mt][0]), "r"(af[mt][1]), "r"(af[mt][2]), "r"(af[mt][3]),
                          "r"(bf[nt][0]), "r"(bf[nt][1]));
                }
        }
        __syncthreads();
    }

#pragma unroll
    for (int mt = 0; mt < 4; mt++) {
#pragma unroll
        for (int nt = 0; nt < 4; nt++) {
            int col = col_blk + n_warp + nt * 8 + tig * 2;
            if (col >= N) continue;
            float bv0 = bias ? bias[col] : 0.f;
            float bv1 = bias ? bias[col + 1] : 0.f;
            int r0 = row_blk + m_warp + mt * 16 + g;
            int r1 = r0 + 8;
            float2 o0, o1;
            o0.x = c[mt][nt][0] + bv0; o0.y = c[mt][nt][1] + bv1;
            o1.x = c[mt][nt][2] + bv0; o1.y = c[mt][nt][3] + bv1;
            if (do_relu) {
                o0.x = fmaxf(o0.x, 0.f); o0.y = fmaxf(o0.y, 0.f);
                o1.x = fmaxf(o1.x, 0.f); o1.y = fmaxf(o1.y, 0.f);
            }
            if (Csrc) {
                // split mode: cols [0,S) -> fp16 Psrc, cols [S,2S) -> fp16 Pdst
                __half2* H = (col < S_DIM) ? (__half2*)Csrc : (__half2*)Cdst;
                int cc = (col < S_DIM) ? col : col - S_DIM;
                if (r0 < M) H[((size_t)r0 * S_DIM + cc) >> 1] = __floats2half2_rn(o0.x, o0.y);
                if (r1 < M) H[((size_t)r1 * S_DIM + cc) >> 1] = __floats2half2_rn(o1.x, o1.y);
            } else {
                if (r0 < M) {
                    *(float2*)&C[(size_t)r0 * N + col] = o0;
                    if (Ch) *(__half2*)&Ch[(size_t)r0 * N + col] = __floats2half2_rn(o0.x, o0.y);
                }
                if (r1 < M) {
                    *(float2*)&C[(size_t)r1 * N + col] = o1;
                    if (Ch) *(__half2*)&Ch[(size_t)r1 * N + col] = __floats2half2_rn(o1.x, o1.y);
                }
            }
        }
    }
}

// ---------------- per-node aggregation, one warp/node, uint4 gathers, unroll x8 ----------------
// state[n] += sum_e relu(h2f(Psrc[src_e]) + h2f(Pdst[n]) + b); writes fp32 + fp16 state.
__global__ __launch_bounds__(256) void aggregate_kernel(const float* __restrict__ b_msg_r) {
    int warp = blockIdx.x * 8 + (threadIdx.x >> 5);
    if (warp >= N_NODES) return;
    int lane = threadIdx.x & 31;

    // base = Pdst[warp][lane*8 .. +7] (fp16) + b
    uint4 bq = __ldg((const uint4*)&g_Pdst[(size_t)warp * S_DIM + lane * 8]);
    float2 d0 = __half22float2(*(__half2*)&bq.x);
    float2 d1 = __half22float2(*(__half2*)&bq.y);
    float2 d2 = __half22float2(*(__half2*)&bq.z);
    float2 d3 = __half22float2(*(__half2*)&bq.w);
    const float4* Bb = (const float4*)b_msg_r;
    float4 bb0 = Bb[lane * 2 + 0];
    float4 bb1 = Bb[lane * 2 + 1];
    float4 base0 = make_float4(d0.x + bb0.x, d0.y + bb0.y, d1.x + bb0.z, d1.y + bb0.w);
    float4 base1 = make_float4(d2.x + bb1.x, d2.y + bb1.y, d3.x + bb1.z, d3.y + bb1.w);

    float4 acc0 = make_float4(0.f, 0.f, 0.f, 0.f);
    float4 acc1 = make_float4(0.f, 0.f, 0.f, 0.f);

    const uint4* Ph = (const uint4*)g_Psrc;   // row = 32 uint4
    int s = g_rowptr[warp];
    int e = g_rowptr[warp + 1];

#define ACC_EDGE(q)                                                          \
    do {                                                                     \
        float2 f0 = __half22float2(*(__half2*)&(q).x);                       \
        float2 f1 = __half22float2(*(__half2*)&(q).y);                       \
        float2 f2 = __half22float2(*(__half2*)&(q).z);                       \
        float2 f3 = __half22float2(*(__half2*)&(q).w);                       \
        acc0.x += fmaxf(f0.x + base0.x, 0.f);                                \
        acc0.y += fmaxf(f0.y + base0.y, 0.f);                                \
        acc0.z += fmaxf(f1.x + base0.z, 0.f);                                \
        acc0.w += fmaxf(f1.y + base0.w, 0.f);                                \
        acc1.x += fmaxf(f2.x + base1.x, 0.f);                                \
        acc1.y += fmaxf(f2.y + base1.y, 0.f);                                \
        acc1.z += fmaxf(f3.x + base1.z, 0.f);                                \
        acc1.w += fmaxf(f3.y + base1.w, 0.f);                                \
    } while (0)

    int i = s;
    for (; i + 8 <= e; i += 8) {
        int sx[8];
#pragma unroll
        for (int u = 0; u < 8; u++) sx[u] = __ldg(&g_esrc[i + u]);
        uint4 q[8];
#pragma unroll
        for (int u = 0; u < 8; u++) q[u] = __ldg(&Ph[(size_t)sx[u] * 32 + lane]);
#pragma unroll
        for (int u = 0; u < 8; u++) ACC_EDGE(q[u]);
    }
    if (i + 4 <= e) {
        int sx[4];
#pragma unroll
        for (int u = 0; u < 4; u++) sx[u] = __ldg(&g_esrc[i + u]);
        uint4 q[4];
#pragma unroll
        for (int u = 0; u < 4; u++) q[u] = __ldg(&Ph[(size_t)sx[u] * 32 + lane]);
#pragma unroll
        for (int u = 0; u < 4; u++) ACC_EDGE(q[u]);
        i += 4;
    }
    for (; i < e; i++) {
        int s0 = __ldg(&g_esrc[i]);
        uint4 q0 = __ldg(&Ph[(size_t)s0 * 32 + lane]);
        ACC_EDGE(q0);
    }
#undef ACC_EDGE

    float4* st = (float4*)&g_state[(size_t)warp * S_DIM + lane * 8];
    float4 s0 = st[0];
    float4 s1 = st[1];
    s0.x += acc0.x; s0.y += acc0.y; s0.z += acc0.z; s0.w += acc0.w;
    s1.x += acc1.x; s1.y += acc1.y; s1.z += acc1.z; s1.w += acc1.w;
    st[0] = s0;
    st[1] = s1;

    // fp16 shadow for the next GEMM
    __half2 h0 = __floats2half2_rn(s0.x, s0.y);
    __half2 h1 = __floats2half2_rn(s0.z, s0.w);
    __half2 h2 = __floats2half2_rn(s1.x, s1.y);
    __half2 h3 = __floats2half2_rn(s1.z, s1.w);
    uint4 pk;
    pk.x = *(unsigned*)&h0; pk.y = *(unsigned*)&h1;
    pk.z = *(unsigned*)&h2; pk.w = *(unsigned*)&h3;
    *(uint4*)&g_state_h[(size_t)warp * S_DIM + lane * 8] = pk;
}

// ---------------- launch ----------------
extern "C" void kernel_launch(void* const* d_in, const int* in_sizes, int n_in,
                              void* d_out, int out_size)
{
    const float* x        = (const float*)d_in[0];
    const int*   eidx     = (const int*)d_in[1];
    // d_in[2] = batch (unused by reference)
    const float* W_in     = (const float*)d_in[3];
    const float* b_in     = (const float*)d_in[4];
    const float* W_msg    = (const float*)d_in[5];   // [ROUNDS, 2S, S]
    const float* b_msg    = (const float*)d_in[6];   // [ROUNDS, S]
    const float* W_out    = (const float*)d_in[7];
    const float* b_out    = (const float*)d_in[8];
    float*       out      = (float*)d_out;

    float*  state;   cudaGetSymbolAddress((void**)&state,   g_state);
    __half* state_h; cudaGetSymbolAddress((void**)&state_h, g_state_h);
    __half* xh;      cudaGetSymbolAddress((void**)&xh,      g_xh);
    __half* Psrc;    cudaGetSymbolAddress((void**)&Psrc,    g_Psrc);
    __half* Pdst;    cudaGetSymbolAddress((void**)&Pdst,    g_Pdst);
    __half* WinT;    cudaGetSymbolAddress((void**)&WinT,    g_WinT);
    __half* WcatT;   cudaGetSymbolAddress((void**)&WcatT,   g_WcatT);
    __half* WoutT;   cudaGetSymbolAddress((void**)&WoutT,   g_WoutT);

    cudaFuncSetAttribute(gemm_f16_kernel,
                         cudaFuncAttributeMaxDynamicSharedMemorySize, SMEM_BYTES);

    // 1) CSR build + fp16 operand prep
    zero_counts_kernel<<<(N_NODES + 255) / 256, 256>>>();
    hist_kernel<<<(N_EDGES + 255) / 256, 256>>>(eidx);
    scan_kernel<<<1, 1024>>>();
    fill_kernel<<<(N_EDGES + 255) / 256, 256>>>(eidx);
    {
        int tot = N_NODES * F_DIM + S_DIM * F_DIM
                + ROUNDS * 2 * S_DIM * S_DIM + L_DIM * S_DIM;
        prep_kernel<<<(tot + 255) / 256, 256>>>(x, W_in, W_msg, W_out);
    }

    // 2) input net: state = relu(x @ W_in + b_in), also fp16 shadow
    {
        dim3 grid(S_DIM / TBN, (N_NODES + TBM - 1) / TBM);
        gemm_f16_kernel<<<grid, 256, SMEM_BYTES>>>(
            xh, WinT, b_in, state, state_h, nullptr, nullptr,
            N_NODES, S_DIM, F_DIM, 1);
    }

    // 3) message rounds
    for (int r = 0; r < ROUNDS; r++) {
        {
            dim3 grid((2 * S_DIM) / TBN, (N_NODES + TBM - 1) / TBM);
            gemm_f16_kernel<<<grid, 256, SMEM_BYTES>>>(
                state_h, WcatT + (size_t)r * 2 * S_DIM * S_DIM, nullptr, nullptr,
                nullptr, Psrc, Pdst, N_NODES, 2 * S_DIM, S_DIM, 0);
        }
        aggregate_kernel<<<(N_NODES + 7) / 8, 256>>>(b_msg + (size_t)r * S_DIM);
    }

    // 4) output net: out = state @ W_out + b_out
    {
        dim3 grid(1, (N_NODES + TBM - 1) / TBM);
        gemm_f16_kernel<<<grid, 256, SMEM_BYTES>>>(
            state_h, WoutT, b_out, out, nullptr, nullptr, nullptr,
            N_NODES, L_DIM, S_DIM, 0);
    }
}

// round 8
// speedup vs baseline: 1.1338x; 1.0634x over previous
#include <cuda_runtime.h>
#include <cuda_fp16.h>

// Problem constants (match reference setup_inputs)
#define N_NODES 25000
#define N_EDGES 400000
#define F_DIM   128
#define S_DIM   256
#define L_DIM   64
#define ROUNDS  4

// ---------------- scratch (static __device__, no allocations) ----------------
__device__ float  g_state[N_NODES * S_DIM];                 // fp32 master
__device__ __half g_state_h[N_NODES * S_DIM];               // fp16 GEMM operand
__device__ __half g_xh[N_NODES * F_DIM];
__device__ __half g_Psrc[N_NODES * S_DIM];                  // fp16 src-half of P
__device__ __half g_Pdst[N_NODES * S_DIM];                  // fp16 dst-half of P
__device__ __half g_WinT[S_DIM * F_DIM];                    // [N=256][K=128]
__device__ __half g_WcatT[ROUNDS * 2 * S_DIM * S_DIM];      // [r][N=512][K=256]
__device__ __half g_WoutT[L_DIM * S_DIM];                   // [N=64][K=256]
__device__ int    g_cnt[N_NODES];
__device__ int    g_cur[N_NODES];
__device__ int    g_rowptr[N_NODES + 1];
__device__ int    g_esrc[N_EDGES];

// ---------------- CSR build (counting sort by dest) ----------------
__global__ void zero_counts_kernel() {
    int i = blockIdx.x * blockDim.x + threadIdx.x;
    if (i < N_NODES) { g_cnt[i] = 0; g_cur[i] = 0; }
}

__global__ void hist_kernel(const int* __restrict__ edge_index) {
    int e = blockIdx.x * blockDim.x + threadIdx.x;
    if (e < N_EDGES) {
        int d = __ldg(&edge_index[N_EDGES + e]);
        atomicAdd(&g_cnt[d], 1);
    }
}

__global__ void scan_kernel() {
    __shared__ int warp_tot[32];
    const int CH = (N_NODES + 1023) / 1024;   // 25
    int t = threadIdx.x;
    int lane = t & 31, wid = t >> 5;
    int base = t * CH;
    int sum = 0;
#pragma unroll
    for (int i = 0; i < CH; i++) {
        int idx = base + i;
        if (idx < N_NODES) sum += g_cnt[idx];
    }
    int v = sum;
#pragma unroll
    for (int off = 1; off < 32; off <<= 1) {
        int n = __shfl_up_sync(0xffffffff, v, off);
        if (lane >= off) v += n;
    }
    if (lane == 31) warp_tot[wid] = v;
    __syncthreads();
    if (wid == 0) {
        int w = warp_tot[lane];
#pragma unroll
        for (int off = 1; off < 32; off <<= 1) {
            int n = __shfl_up_sync(0xffffffff, w, off);
            if (lane >= off) w += n;
        }
        warp_tot[lane] = w;
    }
    __syncthreads();
    int excl = v - sum + (wid > 0 ? warp_tot[wid - 1] : 0);
    int run = excl;
#pragma unroll
    for (int i = 0; i < CH; i++) {
        int idx = base + i;
        if (idx < N_NODES) { g_rowptr[idx] = run; run += g_cnt[idx]; }
    }
    if (t == 1023) g_rowptr[N_NODES] = run;
}

__global__ void fill_kernel(const int* __restrict__ edge_index) {
    int e = blockIdx.x * blockDim.x + threadIdx.x;
    if (e < N_EDGES) {
        int s = __ldg(&edge_index[e]);
        int d = __ldg(&edge_index[N_EDGES + e]);
        int pos = g_rowptr[d] + atomicAdd(&g_cur[d], 1);
        g_esrc[pos] = s;
    }
}

// ---------------- fp16 operand prep (x + all weights in one launch) ----------------
__global__ void prep_kernel(const float* __restrict__ x,
                            const float* __restrict__ W_in,
                            const float* __restrict__ W_msg,
                            const float* __restrict__ W_out) {
    const int NX = N_NODES * F_DIM;
    const int N1 = S_DIM * F_DIM;
    const int N2 = ROUNDS * 2 * S_DIM * S_DIM;
    const int N3 = L_DIM * S_DIM;
    int i = blockIdx.x * blockDim.x + threadIdx.x;
    if (i < NX) {
        g_xh[i] = __float2half(x[i]);
    } else if (i < NX + N1) {
        int t = i - NX;
        int j = t / F_DIM, k = t % F_DIM;
        g_WinT[t] = __float2half(W_in[k * S_DIM + j]);
    } else if (i < NX + N1 + N2) {
        int t = i - NX - N1;
        int r = t / (2 * S_DIM * S_DIM);
        int rem = t % (2 * S_DIM * S_DIM);
        int j = rem / S_DIM;       // 0..511
        int k = rem % S_DIM;
        const float* Wr = W_msg + (size_t)r * 2 * S_DIM * S_DIM;
        float v = (j < S_DIM) ? Wr[k * S_DIM + j] : Wr[(S_DIM + k) * S_DIM + (j - S_DIM)];
        g_WcatT[t] = __float2half(v);
    } else if (i < NX + N1 + N2 + N3) {
        int t = i - NX - N1 - N2;
        int j = t / S_DIM, k = t % S_DIM;
        g_WoutT[t] = __float2half(W_out[k * L_DIM + j]);
    }
}

// ---------------- fp16 tensor-core GEMM, double-buffered ----------------
// C[M,N] = act(A[M,K] @ B^T + bias), B given as [N][K] fp16 (pre-transposed).
// BM=128, BN=128, BK=32, 256 threads (8 warps), warp tile 64x32 via m16n8k16.
#define TBM 128
#define TBN 128
#define TBK 32
#define KP  56
#define TILE_ELEMS (128 * KP)
#define SMEM_BYTES (4 * TILE_ELEMS * 2)

__global__ __launch_bounds__(256, 2) void gemm_f16_kernel(
    const __half* __restrict__ A, const __half* __restrict__ B,
    const float* __restrict__ bias, float* __restrict__ C,
    __half* __restrict__ Ch, __half* __restrict__ Csrc, __half* __restrict__ Cdst,
    int M, int N, int K, int do_relu)
{
    extern __shared__ __half sm[];
    __half* As = sm;                     // [2][128][KP]
    __half* Bs = sm + 2 * TILE_ELEMS;    // [2][128][KP]

    int tid  = threadIdx.x;
    int lane = tid & 31;
    int wid  = tid >> 5;
    int warp_m = wid & 1;
    int warp_n = wid >> 1;
    int m_warp = warp_m * 64;
    int n_warp = warp_n * 32;
    int g   = lane >> 2;
    int tig = lane & 3;

    int row_blk = blockIdx.y * TBM;
    int col_blk = blockIdx.x * TBN;

    float c[4][4][4];
#pragma unroll
    for (int mt = 0; mt < 4; mt++)
#pragma unroll
        for (int nt = 0; nt < 4; nt++)
#pragma unroll
            for (int i = 0; i < 4; i++) c[mt][nt][i] = 0.f;

    int kt  = tid & 3;
    int trow = tid >> 2;

    int nk = K / TBK;
    uint4 av[2], bv[2];
    const uint4 zero4 = make_uint4(0, 0, 0, 0);

#pragma unroll
    for (int p = 0; p < 2; p++) {
        int ar = row_blk + p * 64 + trow;
        av[p] = (ar < M) ? *(const uint4*)&A[(size_t)ar * K + kt * 8] : zero4;
        int br = col_blk + p * 64 + trow;
        bv[p] = (br < N) ? *(const uint4*)&B[(size_t)br * K + kt * 8] : zero4;
    }

    for (int t = 0; t < nk; t++) {
        int cur = t & 1;
        __half* Ac = As + cur * TILE_ELEMS;
        __half* Bc = Bs + cur * TILE_ELEMS;

#pragma unroll
        for (int p = 0; p < 2; p++) {
            int row = p * 64 + trow;
            *(uint4*)&Ac[row * KP + kt * 8] = av[p];
            *(uint4*)&Bc[row * KP + kt * 8] = bv[p];
        }
        __syncthreads();

        if (t + 1 < nk) {
            int k0 = (t + 1) * TBK;
#pragma unroll
            for (int p = 0; p < 2; p++) {
                int ar = row_blk + p * 64 + trow;
                av[p] = (ar < M) ? *(const uint4*)&A[(size_t)ar * K + k0 + kt * 8] : zero4;
                int br = col_blk + p * 64 + trow;
                bv[p] = (br < N) ? *(const uint4*)&B[(size_t)br * K + k0 + kt * 8] : zero4;
            }
        }

#pragma unroll
        for (int ks = 0; ks < TBK; ks += 16) {
            unsigned af[4][4], bf[4][2];
#pragma unroll
            for (int mt = 0; mt < 4; mt++) {
                int mb = m_warp + mt * 16;
                af[mt][0] = *(unsigned*)&Ac[(mb + g) * KP + ks + tig * 2];
                af[mt][1] = *(unsigned*)&Ac[(mb + g + 8) * KP + ks + tig * 2];
                af[mt][2] = *(unsigned*)&Ac[(mb + g) * KP + ks + tig * 2 + 8];
                af[mt][3] = *(unsigned*)&Ac[(mb + g + 8) * KP + ks + tig * 2 + 8];
            }
#pragma unroll
            for (int nt = 0; nt < 4; nt++) {
                int nb = n_warp + nt * 8;
                bf[nt][0] = *(unsigned*)&Bc[(nb + g) * KP + ks + tig * 2];
                bf[nt][1] = *(unsigned*)&Bc[(nb + g) * KP + ks + tig * 2 + 8];
            }
#pragma unroll
            for (int mt = 0; mt < 4; mt++)
#pragma unroll
                for (int nt = 0; nt < 4; nt++) {
                    asm volatile(
                        "mma.sync.aligned.m16n8k16.row.col.f32.f16.f16.f32 "
                        "{%0,%1,%2,%3}, {%4,%5,%6,%7}, {%8,%9}, {%0,%1,%2,%3};"
                        : "+f"(c[mt][nt][0]), "+f"(c[mt][nt][1]),
                          "+f"(c[mt][nt][2]), "+f"(c[mt][nt][3])
                        : "r"(af[mt][0]), "r"(af[mt][1]), "r"(af[mt][2]), "r"(af[mt][3]),
                          "r"(bf[nt][0]), "r"(bf[nt][1]));
                }
        }
        __syncthreads();
    }

#pragma unroll
    for (int mt = 0; mt < 4; mt++) {
#pragma unroll
        for (int nt = 0; nt < 4; nt++) {
            int col = col_blk + n_warp + nt * 8 + tig * 2;
            if (col >= N) continue;
            float bv0 = bias ? bias[col] : 0.f;
            float bv1 = bias ? bias[col + 1] : 0.f;
            int r0 = row_blk + m_warp + mt * 16 + g;
            int r1 = r0 + 8;
            float2 o0, o1;
            o0.x = c[mt][nt][0] + bv0; o0.y = c[mt][nt][1] + bv1;
            o1.x = c[mt][nt][2] + bv0; o1.y = c[mt][nt][3] + bv1;
            if (do_relu) {
                o0.x = fmaxf(o0.x, 0.f); o0.y = fmaxf(o0.y, 0.f);
                o1.x = fmaxf(o1.x, 0.f); o1.y = fmaxf(o1.y, 0.f);
            }
            if (Csrc) {
                // split mode: cols [0,S) -> fp16 Psrc, cols [S,2S) -> fp16 Pdst
                __half2* H = (col < S_DIM) ? (__half2*)Csrc : (__half2*)Cdst;
                int cc = (col < S_DIM) ? col : col - S_DIM;
                if (r0 < M) H[((size_t)r0 * S_DIM + cc) >> 1] = __floats2half2_rn(o0.x, o0.y);
                if (r1 < M) H[((size_t)r1 * S_DIM + cc) >> 1] = __floats2half2_rn(o1.x, o1.y);
            } else {
                if (r0 < M) {
                    *(float2*)&C[(size_t)r0 * N + col] = o0;
                    if (Ch) *(__half2*)&Ch[(size_t)r0 * N + col] = __floats2half2_rn(o0.x, o0.y);
                }
                if (r1 < M) {
                    *(float2*)&C[(size_t)r1 * N + col] = o1;
                    if (Ch) *(__half2*)&Ch[(size_t)r1 * N + col] = __floats2half2_rn(o1.x, o1.y);
                }
            }
        }
    }
}

// ---------------- per-node aggregation, one warp/node, uint4 gathers, unroll x8 ----------------
// state[n] += sum_e relu(h2f(Psrc[src_e]) + h2f(Pdst[n]) + b); writes fp32 + fp16 state.
__global__ __launch_bounds__(256) void aggregate_kernel(const float* __restrict__ b_msg_r) {
    int warp = blockIdx.x * 8 + (threadIdx.x >> 5);
    if (warp >= N_NODES) return;
    int lane = threadIdx.x & 31;

    // base = Pdst[warp][lane*8 .. +7] (fp16) + b
    uint4 bq = __ldg((const uint4*)&g_Pdst[(size_t)warp * S_DIM + lane * 8]);
    float2 d0 = __half22float2(*(__half2*)&bq.x);
    float2 d1 = __half22float2(*(__half2*)&bq.y);
    float2 d2 = __half22float2(*(__half2*)&bq.z);
    float2 d3 = __half22float2(*(__half2*)&bq.w);
    const float4* Bb = (const float4*)b_msg_r;
    float4 bb0 = Bb[lane * 2 + 0];
    float4 bb1 = Bb[lane * 2 + 1];
    float4 base0 = make_float4(d0.x + bb0.x, d0.y + bb0.y, d1.x + bb0.z, d1.y + bb0.w);
    float4 base1 = make_float4(d2.x + bb1.x, d2.y + bb1.y, d3.x + bb1.z, d3.y + bb1.w);

    float4 acc0 = make_float4(0.f, 0.f, 0.f, 0.f);
    float4 acc1 = make_float4(0.f, 0.f, 0.f, 0.f);

    const uint4* Ph = (const uint4*)g_Psrc;   // row = 32 uint4
    int s = g_rowptr[warp];
    int e = g_rowptr[warp + 1];

#define ACC_EDGE(q)                                                          \
    do {                                                                     \
        float2 f0 = __half22float2(*(__half2*)&(q).x);                       \
        float2 f1 = __half22float2(*(__half2*)&(q).y);                       \
        float2 f2 = __half22float2(*(__half2*)&(q).z);                       \
        float2 f3 = __half22float2(*(__half2*)&(q).w);                       \
        acc0.x += fmaxf(f0.x + base0.x, 0.f);                                \
        acc0.y += fmaxf(f0.y + base0.y, 0.f);                                \
        acc0.z += fmaxf(f1.x + base0.z, 0.f);                                \
        acc0.w += fmaxf(f1.y + base0.w, 0.f);                                \
        acc1.x += fmaxf(f2.x + base1.x, 0.f);                                \
        acc1.y += fmaxf(f2.y + base1.y, 0.f);                                \
        acc1.z += fmaxf(f3.x + base1.z, 0.f);                                \
        acc1.w += fmaxf(f3.y + base1.w, 0.f);                                \
    } while (0)

    int i = s;
    for (; i + 8 <= e; i += 8) {
        int sx[8];
#pragma unroll
        for (int u = 0; u < 8; u++) sx[u] = __ldg(&g_esrc[i + u]);
        uint4 q[8];
#pragma unroll
        for (int u = 0; u < 8; u++) q[u] = __ldg(&Ph[(size_t)sx[u] * 32 + lane]);
#pragma unroll
        for (int u = 0; u < 8; u++) ACC_EDGE(q[u]);
    }
    if (i + 4 <= e) {
        int sx[4];
#pragma unroll
        for (int u = 0; u < 4; u++) sx[u] = __ldg(&g_esrc[i + u]);
        uint4 q[4];
#pragma unroll
        for (int u = 0; u < 4; u++) q[u] = __ldg(&Ph[(size_t)sx[u] * 32 + lane]);
#pragma unroll
        for (int u = 0; u < 4; u++) ACC_EDGE(q[u]);
        i += 4;
    }
    for (; i < e; i++) {
        int s0 = __ldg(&g_esrc[i]);
        uint4 q0 = __ldg(&Ph[(size_t)s0 * 32 + lane]);
        ACC_EDGE(q0);
    }
#undef ACC_EDGE

    float4* st = (float4*)&g_state[(size_t)warp * S_DIM + lane * 8];
    float4 s0 = st[0];
    float4 s1 = st[1];
    s0.x += acc0.x; s0.y += acc0.y; s0.z += acc0.z; s0.w += acc0.w;
    s1.x += acc1.x; s1.y += acc1.y; s1.z += acc1.z; s1.w += acc1.w;
    st[0] = s0;
    st[1] = s1;

    // fp16 shadow for the next GEMM
    __half2 h0 = __floats2half2_rn(s0.x, s0.y);
    __half2 h1 = __floats2half2_rn(s0.z, s0.w);
    __half2 h2 = __floats2half2_rn(s1.x, s1.y);
    __half2 h3 = __floats2half2_rn(s1.z, s1.w);
    uint4 pk;
    pk.x = *(unsigned*)&h0; pk.y = *(unsigned*)&h1;
    pk.z = *(unsigned*)&h2; pk.w = *(unsigned*)&h3;
    *(uint4*)&g_state_h[(size_t)warp * S_DIM + lane * 8] = pk;
}

// ---------------- launch ----------------
extern "C" void kernel_launch(void* const* d_in, const int* in_sizes, int n_in,
                              void* d_out, int out_size)
{
    const float* x        = (const float*)d_in[0];
    const int*   eidx     = (const int*)d_in[1];
    // d_in[2] = batch (unused by reference)
    const float* W_in     = (const float*)d_in[3];
    const float* b_in     = (const float*)d_in[4];
    const float* W_msg    = (const float*)d_in[5];   // [ROUNDS, 2S, S]
    const float* b_msg    = (const float*)d_in[6];   // [ROUNDS, S]
    const float* W_out    = (const float*)d_in[7];
    const float* b_out    = (const float*)d_in[8];
    float*       out      = (float*)d_out;

    float*  state;   cudaGetSymbolAddress((void**)&state,   g_state);
    __half* state_h; cudaGetSymbolAddress((void**)&state_h, g_state_h);
    __half* xh;      cudaGetSymbolAddress((void**)&xh,      g_xh);
    __half* Psrc;    cudaGetSymbolAddress((void**)&Psrc,    g_Psrc);
    __half* Pdst;    cudaGetSymbolAddress((void**)&Pdst,    g_Pdst);
    __half* WinT;    cudaGetSymbolAddress((void**)&WinT,    g_WinT);
    __half* WcatT;   cudaGetSymbolAddress((void**)&WcatT,   g_WcatT);
    __half* WoutT;   cudaGetSymbolAddress((void**)&WoutT,   g_WoutT);

    cudaFuncSetAttribute(gemm_f16_kernel,
                         cudaFuncAttributeMaxDynamicSharedMemorySize, SMEM_BYTES);

    // lazy host-side objects (stream/event creation is host-side, not device alloc)
    static cudaStream_t s_side = nullptr;
    static cudaEvent_t  ev_fork = nullptr, ev_join = nullptr;
    if (!s_side) {
        cudaStreamCreateWithFlags(&s_side, cudaStreamNonBlocking);
        cudaEventCreateWithFlags(&ev_fork, cudaEventDisableTiming);
        cudaEventCreateWithFlags(&ev_join, cudaEventDisableTiming);
    }

    // ---- fork: CSR chain on side stream, prep+input GEMM on main stream ----
    cudaEventRecord(ev_fork, 0);
    cudaStreamWaitEvent(s_side, ev_fork, 0);

    // side stream: CSR build (feeds only aggregate)
    zero_counts_kernel<<<(N_NODES + 255) / 256, 256, 0, s_side>>>();
    hist_kernel<<<(N_EDGES + 255) / 256, 256, 0, s_side>>>(eidx);
    scan_kernel<<<1, 1024, 0, s_side>>>();
    fill_kernel<<<(N_EDGES + 255) / 256, 256, 0, s_side>>>(eidx);
    cudaEventRecord(ev_join, s_side);

    // main stream: fp16 operand prep + input net
    {
        int tot = N_NODES * F_DIM + S_DIM * F_DIM
                + ROUNDS * 2 * S_DIM * S_DIM + L_DIM * S_DIM;
        prep_kernel<<<(tot + 255) / 256, 256>>>(x, W_in, W_msg, W_out);
    }
    {
        dim3 grid(S_DIM / TBN, (N_NODES + TBM - 1) / TBM);
        gemm_f16_kernel<<<grid, 256, SMEM_BYTES>>>(
            xh, WinT, b_in, state, state_h, nullptr, nullptr,
            N_NODES, S_DIM, F_DIM, 1);
    }

    // ---- message rounds; CSR join needed only before the first aggregate ----
    for (int r = 0; r < ROUNDS; r++) {
        {
            dim3 grid((2 * S_DIM) / TBN, (N_NODES + TBM - 1) / TBM);
            gemm_f16_kernel<<<grid, 256, SMEM_BYTES>>>(
                state_h, WcatT + (size_t)r * 2 * S_DIM * S_DIM, nullptr, nullptr,
                nullptr, Psrc, Pdst, N_NODES, 2 * S_DIM, S_DIM, 0);
        }
        if (r == 0) cudaStreamWaitEvent(0, ev_join, 0);   // join CSR before first gather
        aggregate_kernel<<<(N_NODES + 7) / 8, 256>>>(b_msg + (size_t)r * S_DIM);
    }

    // output net: out = state @ W_out + b_out
    {
        dim3 grid(1, (N_NODES + TBM - 1) / TBM);
        gemm_f16_kernel<<<grid, 256, SMEM_BYTES>>>(
            state_h, WoutT, b_out, out, nullptr, nullptr, nullptr,
            N_NODES, L_DIM, S_DIM, 0);
    }
}

// round 10
// speedup vs baseline: 1.1743x; 1.0357x over previous
#include <cuda_runtime.h>
#include <cuda_fp16.h>
#include <cstdint>

// Problem constants (match reference setup_inputs)
#define N_NODES 25000
#define N_EDGES 400000
#define F_DIM   128
#define S_DIM   256
#define L_DIM   64
#define ROUNDS  4

// ---------------- scratch (static __device__, no allocations) ----------------
__device__ float  g_state[N_NODES * S_DIM];                 // fp32 master
__device__ __half g_state_h[N_NODES * S_DIM];               // fp16 GEMM operand
__device__ __half g_xh[N_NODES * F_DIM];
__device__ __half g_Psrc[N_NODES * S_DIM];                  // fp16 src-half of P
__device__ __half g_Pdst[N_NODES * S_DIM];                  // fp16 dst-half of P
__device__ __half g_WinT[S_DIM * F_DIM];                    // [N=256][K=128]
__device__ __half g_WcatT[ROUNDS * 2 * S_DIM * S_DIM];      // [r][N=512][K=256]
__device__ __half g_WoutT[L_DIM * S_DIM];                   // [N=64][K=256]
__device__ int    g_cnt[N_NODES];
__device__ int    g_cur[N_NODES];
__device__ int    g_rowptr[N_NODES + 1];
__device__ int    g_esrc[N_EDGES];

// ---------------- CSR build (counting sort by dest) ----------------
__global__ void zero_counts_kernel() {
    int i = blockIdx.x * blockDim.x + threadIdx.x;
    if (i < N_NODES) { g_cnt[i] = 0; g_cur[i] = 0; }
}

__global__ void hist_kernel(const int* __restrict__ edge_index) {
    int e = blockIdx.x * blockDim.x + threadIdx.x;
    if (e < N_EDGES) {
        int d = __ldg(&edge_index[N_EDGES + e]);
        atomicAdd(&g_cnt[d], 1);
    }
}

__global__ void scan_kernel() {
    __shared__ int warp_tot[32];
    const int CH = (N_NODES + 1023) / 1024;   // 25
    int t = threadIdx.x;
    int lane = t & 31, wid = t >> 5;
    int base = t * CH;
    int sum = 0;
#pragma unroll
    for (int i = 0; i < CH; i++) {
        int idx = base + i;
        if (idx < N_NODES) sum += g_cnt[idx];
    }
    int v = sum;
#pragma unroll
    for (int off = 1; off < 32; off <<= 1) {
        int n = __shfl_up_sync(0xffffffff, v, off);
        if (lane >= off) v += n;
    }
    if (lane == 31) warp_tot[wid] = v;
    __syncthreads();
    if (wid == 0) {
        int w = warp_tot[lane];
#pragma unroll
        for (int off = 1; off < 32; off <<= 1) {
            int n = __shfl_up_sync(0xffffffff, w, off);
            if (lane >= off) w += n;
        }
        warp_tot[lane] = w;
    }
    __syncthreads();
    int excl = v - sum + (wid > 0 ? warp_tot[wid - 1] : 0);
    int run = excl;
#pragma unroll
    for (int i = 0; i < CH; i++) {
        int idx = base + i;
        if (idx < N_NODES) { g_rowptr[idx] = run; run += g_cnt[idx]; }
    }
    if (t == 1023) g_rowptr[N_NODES] = run;
}

__global__ void fill_kernel(const int* __restrict__ edge_index) {
    int e = blockIdx.x * blockDim.x + threadIdx.x;
    if (e < N_EDGES) {
        int s = __ldg(&edge_index[e]);
        int d = __ldg(&edge_index[N_EDGES + e]);
        int pos = g_rowptr[d] + atomicAdd(&g_cur[d], 1);
        g_esrc[pos] = s;
    }
}

// ---------------- fp16 operand prep (x + all weights in one launch) ----------------
__global__ void prep_kernel(const float* __restrict__ x,
                            const float* __restrict__ W_in,
                            const float* __restrict__ W_msg,
                            const float* __restrict__ W_out) {
    const int NX = N_NODES * F_DIM;
    const int N1 = S_DIM * F_DIM;
    const int N2 = ROUNDS * 2 * S_DIM * S_DIM;
    const int N3 = L_DIM * S_DIM;
    int i = blockIdx.x * blockDim.x + threadIdx.x;
    if (i < NX) {
        g_xh[i] = __float2half(x[i]);
    } else if (i < NX + N1) {
        int t = i - NX;
        int j = t / F_DIM, k = t % F_DIM;
        g_WinT[t] = __float2half(W_in[k * S_DIM + j]);
    } else if (i < NX + N1 + N2) {
        int t = i - NX - N1;
        int r = t / (2 * S_DIM * S_DIM);
        int rem = t % (2 * S_DIM * S_DIM);
        int j = rem / S_DIM;       // 0..511
        int k = rem % S_DIM;
        const float* Wr = W_msg + (size_t)r * 2 * S_DIM * S_DIM;
        float v = (j < S_DIM) ? Wr[k * S_DIM + j] : Wr[(S_DIM + k) * S_DIM + (j - S_DIM)];
        g_WcatT[t] = __float2half(v);
    } else if (i < NX + N1 + N2 + N3) {
        int t = i - NX - N1 - N2;
        int j = t / S_DIM, k = t % S_DIM;
        g_WoutT[t] = __float2half(W_out[k * L_DIM + j]);
    }
}

// ---------------- fp16 tensor-core GEMM, cp.async 3-stage pipeline ----------------
// C[M,N] = act(A[M,K] @ B^T + bias), B given as [N][K] fp16 (pre-transposed).
// BM=128, BN=128, BK=32, 256 threads (8 warps), warp tile 64x32 via m16n8k16.
#define TBM 128
#define TBN 128
#define TBK 32
#define KP  56
#define NSTAGE 3
#define TILE_ELEMS (128 * KP)
#define SMEM_BYTES (NSTAGE * 2 * TILE_ELEMS * 2)

__device__ __forceinline__ void cp_async16(unsigned int dst, const void* src, int nbytes) {
    asm volatile("cp.async.ca.shared.global [%0], [%1], 16, %2;\n"
                 :: "r"(dst), "l"(src), "r"(nbytes));
}
__device__ __forceinline__ void cp_async_commit() {
    asm volatile("cp.async.commit_group;\n");
}
template <int N>
__device__ __forceinline__ void cp_async_wait() {
    asm volatile("cp.async.wait_group %0;\n" :: "n"(N));
}

__global__ __launch_bounds__(256, 2) void gemm_f16_kernel(
    const __half* __restrict__ A, const __half* __restrict__ B,
    const float* __restrict__ bias, float* __restrict__ C,
    __half* __restrict__ Ch, __half* __restrict__ Csrc, __half* __restrict__ Cdst,
    int M, int N, int K, int do_relu)
{
    extern __shared__ __half sm[];
    __half* As = sm;                               // [NSTAGE][128][KP]
    __half* Bs = sm + NSTAGE * TILE_ELEMS;         // [NSTAGE][128][KP]

    int tid  = threadIdx.x;
    int lane = tid & 31;
    int wid  = tid >> 5;
    int warp_m = wid & 1;
    int warp_n = wid >> 1;
    int m_warp = warp_m * 64;
    int n_warp = warp_n * 32;
    int g   = lane >> 2;
    int tig = lane & 3;

    int row_blk = blockIdx.y * TBM;
    int col_blk = blockIdx.x * TBN;

    float c[4][4][4];
#pragma unroll
    for (int mt = 0; mt < 4; mt++)
#pragma unroll
        for (int nt = 0; nt < 4; nt++)
#pragma unroll
            for (int i = 0; i < 4; i++) c[mt][nt][i] = 0.f;

    // cp.async indexing: 16B chunk = 8 halfs; 4 chunks per 32-half k-row;
    // thread -> (chunk kt, row trow), rows 0..63 + pass p*64
    int kt   = tid & 3;
    int trow = tid >> 2;

    unsigned int As_u32 = (unsigned int)__cvta_generic_to_shared(As);
    unsigned int Bs_u32 = (unsigned int)__cvta_generic_to_shared(Bs);

    int nk = K / TBK;

    // issue loads for tile t into stage s
    auto issue_tile = [&](int t, int s) {
        int k0 = t * TBK;
#pragma unroll
        for (int p = 0; p < 2; p++) {
            int row = p * 64 + trow;
            unsigned int dA = As_u32 + (unsigned int)(s * TILE_ELEMS + row * KP + kt * 8) * 2u;
            int ar = row_blk + row;
            cp_async16(dA, &A[(size_t)ar * K + k0 + kt * 8], (ar < M) ? 16 : 0);
            unsigned int dB = Bs_u32 + (unsigned int)(s * TILE_ELEMS + row * KP + kt * 8) * 2u;
            int br = col_blk + row;
            cp_async16(dB, &B[(size_t)br * K + k0 + kt * 8], (br < N) ? 16 : 0);
        }
        cp_async_commit();
    };

    // prologue: stages 0 and 1
    issue_tile(0, 0);
    if (nk > 1) issue_tile(1, 1);
    else cp_async_commit();   // keep group count consistent

    for (int t = 0; t < nk; t++) {
        cp_async_wait<1>();           // oldest outstanding (tile t) complete
        __syncthreads();

        int cur = t % NSTAGE;
        __half* Ac = As + cur * TILE_ELEMS;
        __half* Bc = Bs + cur * TILE_ELEMS;

        if (t + 2 < nk) issue_tile(t + 2, (t + 2) % NSTAGE);
        else cp_async_commit();       // keep pipeline depth bookkeeping uniform

#pragma unroll
        for (int ks = 0; ks < TBK; ks += 16) {
            unsigned af[4][4], bf[4][2];
#pragma unroll
            for (int mt = 0; mt < 4; mt++) {
                int mb = m_warp + mt * 16;
                af[mt][0] = *(unsigned*)&Ac[(mb + g) * KP + ks + tig * 2];
                af[mt][1] = *(unsigned*)&Ac[(mb + g + 8) * KP + ks + tig * 2];
                af[mt][2] = *(unsigned*)&Ac[(mb + g) * KP + ks + tig * 2 + 8];
                af[mt][3] = *(unsigned*)&Ac[(mb + g + 8) * KP + ks + tig * 2 + 8];
            }
#pragma unroll
            for (int nt = 0; nt < 4; nt++) {
                int nb = n_warp + nt * 8;
                bf[nt][0] = *(unsigned*)&Bc[(nb + g) * KP + ks + tig * 2];
                bf[nt][1] = *(unsigned*)&Bc[(nb + g) * KP + ks + tig * 2 + 8];
            }
#pragma unroll
            for (int mt = 0; mt < 4; mt++)
#pragma unroll
                for (int nt = 0; nt < 4; nt++) {
                    asm volatile(
                        "mma.sync.aligned.m16n8k16.row.col.f32.f16.f16.f32 "
                        "{%0,%1,%2,%3}, {%4,%5,%6,%7}, {%8,%9}, {%0,%1,%2,%3};"
                        : "+f"(c[mt][nt][0]), "+f"(c[mt][nt][1]),
                          "+f"(c[mt][nt][2]), "+f"(c[mt][nt][3])
                        : "r"(af[mt][0]), "r"(af[mt][1]), "r"(af[mt][2]), "r"(af[mt][3]),
                          "r"(bf[nt][0]), "r"(bf[nt][1]));
                }
        }
        __syncthreads();
    }

    // epilogue
#pragma unroll
    for (int mt = 0; mt < 4; mt++) {
#pragma unroll
        for (int nt = 0; nt < 4; nt++) {
            int col = col_blk + n_warp + nt * 8 + tig * 2;
            if (col >= N) continue;
            float bv0 = bias ? bias[col] : 0.f;
            float bv1 = bias ? bias[col + 1] : 0.f;
            int r0 = row_blk + m_warp + mt * 16 + g;
            int r1 = r0 + 8;
            float2 o0, o1;
            o0.x = c[mt][nt][0] + bv0; o0.y = c[mt][nt][1] + bv1;
            o1.x = c[mt][nt][2] + bv0; o1.y = c[mt][nt][3] + bv1;
            if (do_relu) {
                o0.x = fmaxf(o0.x, 0.f); o0.y = fmaxf(o0.y, 0.f);
                o1.x = fmaxf(o1.x, 0.f); o1.y = fmaxf(o1.y, 0.f);
            }
            if (Csrc) {
                // split mode: cols [0,S) -> fp16 Psrc, cols [S,2S) -> fp16 Pdst
                __half2* H = (col < S_DIM) ? (__half2*)Csrc : (__half2*)Cdst;
                int cc = (col < S_DIM) ? col : col - S_DIM;
                if (r0 < M) H[((size_t)r0 * S_DIM + cc) >> 1] = __floats2half2_rn(o0.x, o0.y);
                if (r1 < M) H[((size_t)r1 * S_DIM + cc) >> 1] = __floats2half2_rn(o1.x, o1.y);
            } else {
                if (r0 < M) {
                    *(float2*)&C[(size_t)r0 * N + col] = o0;
                    if (Ch) *(__half2*)&Ch[(size_t)r0 * N + col] = __floats2half2_rn(o0.x, o0.y);
                }
                if (r1 < M) {
                    *(float2*)&C[(size_t)r1 * N + col] = o1;
                    if (Ch) *(__half2*)&Ch[(size_t)r1 * N + col] = __floats2half2_rn(o1.x, o1.y);
                }
            }
        }
    }
}

// ---------------- per-node aggregation, one warp/node, uint4 gathers, unroll x8 ----------------
// state[n] += sum_e relu(h2f(Psrc[src_e]) + h2f(Pdst[n]) + b); writes fp32 + fp16 state.
__global__ __launch_bounds__(256) void aggregate_kernel(const float* __restrict__ b_msg_r) {
    int warp = blockIdx.x * 8 + (threadIdx.x >> 5);
    if (warp >= N_NODES) return;
    int lane = threadIdx.x & 31;

    // base = Pdst[warp][lane*8 .. +7] (fp16) + b
    uint4 bq = __ldg((const uint4*)&g_Pdst[(size_t)warp * S_DIM + lane * 8]);
    float2 d0 = __half22float2(*(__half2*)&bq.x);
    float2 d1 = __half22float2(*(__half2*)&bq.y);
    float2 d2 = __half22float2(*(__half2*)&bq.z);
    float2 d3 = __half22float2(*(__half2*)&bq.w);
    const float4* Bb = (const float4*)b_msg_r;
    float4 bb0 = Bb[lane * 2 + 0];
    float4 bb1 = Bb[lane * 2 + 1];
    float4 base0 = make_float4(d0.x + bb0.x, d0.y + bb0.y, d1.x + bb0.z, d1.y + bb0.w);
    float4 base1 = make_float4(d2.x + bb1.x, d2.y + bb1.y, d3.x + bb1.z, d3.y + bb1.w);

    float4 acc0 = make_float4(0.f, 0.f, 0.f, 0.f);
    float4 acc1 = make_float4(0.f, 0.f, 0.f, 0.f);

    const uint4* Ph = (const uint4*)g_Psrc;   // row = 32 uint4
    int s = g_rowptr[warp];
    int e = g_rowptr[warp + 1];

#define ACC_EDGE(q)                                                          \
    do {                                                                     \
        float2 f0 = __half22float2(*(__half2*)&(q).x);                       \
        float2 f1 = __half22float2(*(__half2*)&(q).y);                       \
        float2 f2 = __half22float2(*(__half2*)&(q).z);                       \
        float2 f3 = __half22float2(*(__half2*)&(q).w);                       \
        acc0.x += fmaxf(f0.x + base0.x, 0.f);                                \
        acc0.y += fmaxf(f0.y + base0.y, 0.f);                                \
        acc0.z += fmaxf(f1.x + base0.z, 0.f);                                \
        acc0.w += fmaxf(f1.y + base0.w, 0.f);                                \
        acc1.x += fmaxf(f2.x + base1.x, 0.f);                                \
        acc1.y += fmaxf(f2.y + base1.y, 0.f);                                \
        acc1.z += fmaxf(f3.x + base1.z, 0.f);                                \
        acc1.w += fmaxf(f3.y + base1.w, 0.f);                                \
    } while (0)

    int i = s;
    for (; i + 8 <= e; i += 8) {
        int sx[8];
#pragma unroll
        for (int u = 0; u < 8; u++) sx[u] = __ldg(&g_esrc[i + u]);
        uint4 q[8];
#pragma unroll
        for (int u = 0; u < 8; u++) q[u] = __ldg(&Ph[(size_t)sx[u] * 32 + lane]);
#pragma unroll
        for (int u = 0; u < 8; u++) ACC_EDGE(q[u]);
    }
    if (i + 4 <= e) {
        int sx[4];
#pragma unroll
        for (int u = 0; u < 4; u++) sx[u] = __ldg(&g_esrc[i + u]);
        uint4 q[4];
#pragma unroll
        for (int u = 0; u < 4; u++) q[u] = __ldg(&Ph[(size_t)sx[u] * 32 + lane]);
#pragma unroll
        for (int u = 0; u < 4; u++) ACC_EDGE(q[u]);
        i += 4;
    }
    for (; i < e; i++) {
        int s0 = __ldg(&g_esrc[i]);
        uint4 q0 = __ldg(&Ph[(size_t)s0 * 32 + lane]);
        ACC_EDGE(q0);
    }
#undef ACC_EDGE

    float4* st = (float4*)&g_state[(size_t)warp * S_DIM + lane * 8];
    float4 s0 = st[0];
    float4 s1 = st[1];
    s0.x += acc0.x; s0.y += acc0.y; s0.z += acc0.z; s0.w += acc0.w;
    s1.x += acc1.x; s1.y += acc1.y; s1.z += acc1.z; s1.w += acc1.w;
    st[0] = s0;
    st[1] = s1;

    // fp16 shadow for the next GEMM
    __half2 h0 = __floats2half2_rn(s0.x, s0.y);
    __half2 h1 = __floats2half2_rn(s0.z, s0.w);
    __half2 h2 = __floats2half2_rn(s1.x, s1.y);
    __half2 h3 = __floats2half2_rn(s1.z, s1.w);
    uint4 pk;
    pk.x = *(unsigned*)&h0; pk.y = *(unsigned*)&h1;
    pk.z = *(unsigned*)&h2; pk.w = *(unsigned*)&h3;
    *(uint4*)&g_state_h[(size_t)warp * S_DIM + lane * 8] = pk;
}

// ---------------- launch ----------------
extern "C" void kernel_launch(void* const* d_in, const int* in_sizes, int n_in,
                              void* d_out, int out_size)
{
    const float* x        = (const float*)d_in[0];
    const int*   eidx     = (const int*)d_in[1];
    // d_in[2] = batch (unused by reference)
    const float* W_in     = (const float*)d_in[3];
    const float* b_in     = (const float*)d_in[4];
    const float* W_msg    = (const float*)d_in[5];   // [ROUNDS, 2S, S]
    const float* b_msg    = (const float*)d_in[6];   // [ROUNDS, S]
    const float* W_out    = (const float*)d_in[7];
    const float* b_out    = (const float*)d_in[8];
    float*       out      = (float*)d_out;

    float*  state;   cudaGetSymbolAddress((void**)&state,   g_state);
    __half* state_h; cudaGetSymbolAddress((void**)&state_h, g_state_h);
    __half* xh;      cudaGetSymbolAddress((void**)&xh,      g_xh);
    __half* Psrc;    cudaGetSymbolAddress((void**)&Psrc,    g_Psrc);
    __half* Pdst;    cudaGetSymbolAddress((void**)&Pdst,    g_Pdst);
    __half* WinT;    cudaGetSymbolAddress((void**)&WinT,    g_WinT);
    __half* WcatT;   cudaGetSymbolAddress((void**)&WcatT,   g_WcatT);
    __half* WoutT;   cudaGetSymbolAddress((void**)&WoutT,   g_WoutT);

    cudaFuncSetAttribute(gemm_f16_kernel,
                         cudaFuncAttributeMaxDynamicSharedMemorySize, SMEM_BYTES);

    // lazy host-side objects (stream/event creation is host-side, not device alloc)
    static cudaStream_t s_side = nullptr;
    static cudaEvent_t  ev_fork = nullptr, ev_join = nullptr;
    if (!s_side) {
        cudaStreamCreateWithFlags(&s_side, cudaStreamNonBlocking);
        cudaEventCreateWithFlags(&ev_fork, cudaEventDisableTiming);
        cudaEventCreateWithFlags(&ev_join, cudaEventDisableTiming);
    }

    // ---- fork: CSR chain on side stream, prep+input GEMM on main stream ----
    cudaEventRecord(ev_fork, 0);
    cudaStreamWaitEvent(s_side, ev_fork, 0);

    // side stream: CSR build (feeds only aggregate)
    zero_counts_kernel<<<(N_NODES + 255) / 256, 256, 0, s_side>>>();
    hist_kernel<<<(N_EDGES + 255) / 256, 256, 0, s_side>>>(eidx);
    scan_kernel<<<1, 1024, 0, s_side>>>();
    fill_kernel<<<(N_EDGES + 255) / 256, 256, 0, s_side>>>(eidx);
    cudaEventRecord(ev_join, s_side);

    // main stream: fp16 operand prep + input net
    {
        int tot = N_NODES * F_DIM + S_DIM * F_DIM
                + ROUNDS * 2 * S_DIM * S_DIM + L_DIM * S_DIM;
        prep_kernel<<<(tot + 255) / 256, 256>>>(x, W_in, W_msg, W_out);
    }
    {
        dim3 grid(S_DIM / TBN, (N_NODES + TBM - 1) / TBM);
        gemm_f16_kernel<<<grid, 256, SMEM_BYTES>>>(
            xh, WinT, b_in, state, state_h, nullptr, nullptr,
            N_NODES, S_DIM, F_DIM, 1);
    }

    // ---- message rounds; CSR join needed only before the first aggregate ----
    for (int r = 0; r < ROUNDS; r++) {
        {
            dim3 grid((2 * S_DIM) / TBN, (N_NODES + TBM - 1) / TBM);
            gemm_f16_kernel<<<grid, 256, SMEM_BYTES>>>(
                state_h, WcatT + (size_t)r * 2 * S_DIM * S_DIM, nullptr, nullptr,
                nullptr, Psrc, Pdst, N_NODES, 2 * S_DIM, S_DIM, 0);
        }
        if (r == 0) cudaStreamWaitEvent(0, ev_join, 0);   // join CSR before first gather
        aggregate_kernel<<<(N_NODES + 7) / 8, 256>>>(b_msg + (size_t)r * S_DIM);
    }

    // output net: out = state @ W_out + b_out
    {
        dim3 grid(1, (N_NODES + TBM - 1) / TBM);
        gemm_f16_kernel<<<grid, 256, SMEM_BYTES>>>(
            state_h, WoutT, b_out, out, nullptr, nullptr, nullptr,
            N_NODES, L_DIM, S_DIM, 0);
    }
}

// round 11
// speedup vs baseline: 1.2462x; 1.0613x over previous
#include <cuda_runtime.h>
#include <cuda_fp16.h>
#include <cstdint>

// Problem constants (match reference setup_inputs)
#define N_NODES 25000
#define N_EDGES 400000
#define F_DIM   128
#define S_DIM   256
#define L_DIM   64
#define ROUNDS  4

// ---------------- scratch (static __device__, no allocations) ----------------
__device__ float  g_state[N_NODES * S_DIM];                 // fp32 master
__device__ __half g_state_h[N_NODES * S_DIM];               // fp16 GEMM operand
__device__ __half g_xh[N_NODES * F_DIM];
__device__ __half g_Psrc[N_NODES * S_DIM];                  // fp16 src-half of P
__device__ __half g_Pdst[N_NODES * S_DIM];                  // fp16 dst-half of P
__device__ __half g_WinT[S_DIM * F_DIM];                    // [N=256][K=128]
__device__ __half g_WcatT[ROUNDS * 2 * S_DIM * S_DIM];      // [r][N=512][K=256]
__device__ __half g_WoutT[L_DIM * S_DIM];                   // [N=64][K=256]
__device__ int    g_cnt[N_NODES];
__device__ int    g_cur[N_NODES];
__device__ int    g_rowptr[N_NODES + 1];
__device__ int    g_esrc[N_EDGES];

// ---------------- CSR build (counting sort by dest) ----------------
__global__ void zero_counts_kernel() {
    int i = blockIdx.x * blockDim.x + threadIdx.x;
    if (i < N_NODES) { g_cnt[i] = 0; g_cur[i] = 0; }
}

__global__ void hist_kernel(const int* __restrict__ edge_index) {
    int e = blockIdx.x * blockDim.x + threadIdx.x;
    if (e < N_EDGES) {
        int d = __ldg(&edge_index[N_EDGES + e]);
        atomicAdd(&g_cnt[d], 1);
    }
}

__global__ void scan_kernel() {
    __shared__ int warp_tot[32];
    const int CH = (N_NODES + 1023) / 1024;   // 25
    int t = threadIdx.x;
    int lane = t & 31, wid = t >> 5;
    int base = t * CH;
    int sum = 0;
#pragma unroll
    for (int i = 0; i < CH; i++) {
        int idx = base + i;
        if (idx < N_NODES) sum += g_cnt[idx];
    }
    int v = sum;
#pragma unroll
    for (int off = 1; off < 32; off <<= 1) {
        int n = __shfl_up_sync(0xffffffff, v, off);
        if (lane >= off) v += n;
    }
    if (lane == 31) warp_tot[wid] = v;
    __syncthreads();
    if (wid == 0) {
        int w = warp_tot[lane];
#pragma unroll
        for (int off = 1; off < 32; off <<= 1) {
            int n = __shfl_up_sync(0xffffffff, w, off);
            if (lane >= off) w += n;
        }
        warp_tot[lane] = w;
    }
    __syncthreads();
    int excl = v - sum + (wid > 0 ? warp_tot[wid - 1] : 0);
    int run = excl;
#pragma unroll
    for (int i = 0; i < CH; i++) {
        int idx = base + i;
        if (idx < N_NODES) { g_rowptr[idx] = run; run += g_cnt[idx]; }
    }
    if (t == 1023) g_rowptr[N_NODES] = run;
}

__global__ void fill_kernel(const int* __restrict__ edge_index) {
    int e = blockIdx.x * blockDim.x + threadIdx.x;
    if (e < N_EDGES) {
        int s = __ldg(&edge_index[e]);
        int d = __ldg(&edge_index[N_EDGES + e]);
        int pos = g_rowptr[d] + atomicAdd(&g_cur[d], 1);
        g_esrc[pos] = s;
    }
}

// ---------------- fp16 operand prep (x + all weights in one launch) ----------------
__global__ void prep_kernel(const float* __restrict__ x,
                            const float* __restrict__ W_in,
                            const float* __restrict__ W_msg,
                            const float* __restrict__ W_out) {
    const int NX = N_NODES * F_DIM;
    const int N1 = S_DIM * F_DIM;
    const int N2 = ROUNDS * 2 * S_DIM * S_DIM;
    const int N3 = L_DIM * S_DIM;
    int i = blockIdx.x * blockDim.x + threadIdx.x;
    if (i < NX) {
        g_xh[i] = __float2half(x[i]);
    } else if (i < NX + N1) {
        int t = i - NX;
        int j = t / F_DIM, k = t % F_DIM;
        g_WinT[t] = __float2half(W_in[k * S_DIM + j]);
    } else if (i < NX + N1 + N2) {
        int t = i - NX - N1;
        int r = t / (2 * S_DIM * S_DIM);
        int rem = t % (2 * S_DIM * S_DIM);
        int j = rem / S_DIM;       // 0..511
        int k = rem % S_DIM;
        const float* Wr = W_msg + (size_t)r * 2 * S_DIM * S_DIM;
        float v = (j < S_DIM) ? Wr[k * S_DIM + j] : Wr[(S_DIM + k) * S_DIM + (j - S_DIM)];
        g_WcatT[t] = __float2half(v);
    } else if (i < NX + N1 + N2 + N3) {
        int t = i - NX - N1 - N2;
        int j = t / S_DIM, k = t % S_DIM;
        g_WoutT[t] = __float2half(W_out[k * L_DIM + j]);
    }
}

// ---------------- fp16 tensor-core GEMM: cp.async 3-stage + ldmatrix frags ----------------
// C[M,N] = act(A[M,K] @ B^T + bias), B given as [N][K] fp16 (pre-transposed).
// BM=128, BN=128, BK=32, 256 threads (8 warps), warp tile 64x32 via m16n8k16.
#define TBM 128
#define TBN 128
#define TBK 32
#define KP  56
#define NSTAGE 3
#define TILE_ELEMS (128 * KP)
#define SMEM_BYTES (NSTAGE * 2 * TILE_ELEMS * 2)

__device__ __forceinline__ void cp_async16(unsigned int dst, const void* src, int nbytes) {
    asm volatile("cp.async.ca.shared.global [%0], [%1], 16, %2;\n"
                 :: "r"(dst), "l"(src), "r"(nbytes));
}
__device__ __forceinline__ void cp_async_commit() {
    asm volatile("cp.async.commit_group;\n");
}
template <int N>
__device__ __forceinline__ void cp_async_wait() {
    asm volatile("cp.async.wait_group %0;\n" :: "n"(N));
}
__device__ __forceinline__ void ldsm_x4(unsigned& r0, unsigned& r1, unsigned& r2, unsigned& r3,
                                        unsigned int addr) {
    asm volatile("ldmatrix.sync.aligned.m8n8.x4.shared.b16 {%0,%1,%2,%3}, [%4];"
                 : "=r"(r0), "=r"(r1), "=r"(r2), "=r"(r3) : "r"(addr));
}

__global__ __launch_bounds__(256, 2) void gemm_f16_kernel(
    const __half* __restrict__ A, const __half* __restrict__ B,
    const float* __restrict__ bias, float* __restrict__ C,
    __half* __restrict__ Ch, __half* __restrict__ Csrc, __half* __restrict__ Cdst,
    int M, int N, int K, int do_relu)
{
    extern __shared__ __half sm[];
    __half* As = sm;                               // [NSTAGE][128][KP]
    __half* Bs = sm + NSTAGE * TILE_ELEMS;         // [NSTAGE][128][KP]

    int tid  = threadIdx.x;
    int lane = tid & 31;
    int wid  = tid >> 5;
    int warp_m = wid & 1;
    int warp_n = wid >> 1;
    int m_warp = warp_m * 64;
    int n_warp = warp_n * 32;
    int g   = lane >> 2;
    int tig = lane & 3;

    int row_blk = blockIdx.y * TBM;
    int col_blk = blockIdx.x * TBN;

    float c[4][4][4];
#pragma unroll
    for (int mt = 0; mt < 4; mt++)
#pragma unroll
        for (int nt = 0; nt < 4; nt++)
#pragma unroll
            for (int i = 0; i < 4; i++) c[mt][nt][i] = 0.f;

    // cp.async indexing: 16B chunk = 8 halfs; 4 chunks per 32-half k-row
    int kt   = tid & 3;
    int trow = tid >> 2;

    unsigned int As_u32 = (unsigned int)__cvta_generic_to_shared(As);
    unsigned int Bs_u32 = (unsigned int)__cvta_generic_to_shared(Bs);

    // ldmatrix per-lane address components
    // A x4: matrices (r0,k0),(r8,k0),(r0,k8),(r8,k8)
    int a_row_off = (lane & 7) + ((lane >> 3) & 1) * 8;   // row within 16-row mt block
    int a_kk_off  = (lane >> 4) * 8;                      // 0 or 8
    // B x4: matrices (n0,k0),(n0,k8),(n8,k0),(n8,k8)  -> covers nt pair
    int b_row_off = (lane & 7) + (lane >> 4) * 8;
    int b_kk_off  = ((lane >> 3) & 1) * 8;

    int nk = K / TBK;

    // issue loads for tile t into stage s
    auto issue_tile = [&](int t, int s) {
        int k0 = t * TBK;
#pragma unroll
        for (int p = 0; p < 2; p++) {
            int row = p * 64 + trow;
            unsigned int dA = As_u32 + (unsigned int)(s * TILE_ELEMS + row * KP + kt * 8) * 2u;
            int ar = row_blk + row;
            cp_async16(dA, &A[(size_t)ar * K + k0 + kt * 8], (ar < M) ? 16 : 0);
            unsigned int dB = Bs_u32 + (unsigned int)(s * TILE_ELEMS + row * KP + kt * 8) * 2u;
            int br = col_blk + row;
            cp_async16(dB, &B[(size_t)br * K + k0 + kt * 8], (br < N) ? 16 : 0);
        }
        cp_async_commit();
    };

    // prologue: stages 0 and 1
    issue_tile(0, 0);
    if (nk > 1) issue_tile(1, 1);
    else cp_async_commit();   // keep group count consistent

    for (int t = 0; t < nk; t++) {
        cp_async_wait<1>();           // oldest outstanding (tile t) complete
        __syncthreads();

        int cur = t % NSTAGE;
        unsigned int Ac_u32 = As_u32 + (unsigned int)(cur * TILE_ELEMS) * 2u;
        unsigned int Bc_u32 = Bs_u32 + (unsigned int)(cur * TILE_ELEMS) * 2u;

        if (t + 2 < nk) issue_tile(t + 2, (t + 2) % NSTAGE);
        else cp_async_commit();       // keep pipeline depth bookkeeping uniform

#pragma unroll
        for (int ks = 0; ks < TBK; ks += 16) {
            unsigned af[4][4], bf[4][2];
#pragma unroll
            for (int mt = 0; mt < 4; mt++) {
                int mb = m_warp + mt * 16;
                unsigned int aaddr = Ac_u32
                    + (unsigned int)((mb + a_row_off) * KP + ks + a_kk_off) * 2u;
                ldsm_x4(af[mt][0], af[mt][1], af[mt][2], af[mt][3], aaddr);
            }
#pragma unroll
            for (int ntp = 0; ntp < 2; ntp++) {
                int nb = n_warp + ntp * 16;
                unsigned int baddr = Bc_u32
                    + (unsigned int)((nb + b_row_off) * KP + ks + b_kk_off) * 2u;
                ldsm_x4(bf[ntp * 2][0], bf[ntp * 2][1],
                        bf[ntp * 2 + 1][0], bf[ntp * 2 + 1][1], baddr);
            }
#pragma unroll
            for (int mt = 0; mt < 4; mt++)
#pragma unroll
                for (int nt = 0; nt < 4; nt++) {
                    asm volatile(
                        "mma.sync.aligned.m16n8k16.row.col.f32.f16.f16.f32 "
                        "{%0,%1,%2,%3}, {%4,%5,%6,%7}, {%8,%9}, {%0,%1,%2,%3};"
                        : "+f"(c[mt][nt][0]), "+f"(c[mt][nt][1]),
                          "+f"(c[mt][nt][2]), "+f"(c[mt][nt][3])
                        : "r"(af[mt][0]), "r"(af[mt][1]), "r"(af[mt][2]), "r"(af[mt][3]),
                          "r"(bf[nt][0]), "r"(bf[nt][1]));
                }
        }
        __syncthreads();
    }

    // epilogue
#pragma unroll
    for (int mt = 0; mt < 4; mt++) {
#pragma unroll
        for (int nt = 0; nt < 4; nt++) {
            int col = col_blk + n_warp + nt * 8 + tig * 2;
            if (col >= N) continue;
            float bv0 = bias ? bias[col] : 0.f;
            float bv1 = bias ? bias[col + 1] : 0.f;
            int r0 = row_blk + m_warp + mt * 16 + g;
            int r1 = r0 + 8;
            float2 o0, o1;
            o0.x = c[mt][nt][0] + bv0; o0.y = c[mt][nt][1] + bv1;
            o1.x = c[mt][nt][2] + bv0; o1.y = c[mt][nt][3] + bv1;
            if (do_relu) {
                o0.x = fmaxf(o0.x, 0.f); o0.y = fmaxf(o0.y, 0.f);
                o1.x = fmaxf(o1.x, 0.f); o1.y = fmaxf(o1.y, 0.f);
            }
            if (Csrc) {
                // split mode: cols [0,S) -> fp16 Psrc, cols [S,2S) -> fp16 Pdst
                __half2* H = (col < S_DIM) ? (__half2*)Csrc : (__half2*)Cdst;
                int cc = (col < S_DIM) ? col : col - S_DIM;
                if (r0 < M) H[((size_t)r0 * S_DIM + cc) >> 1] = __floats2half2_rn(o0.x, o0.y);
                if (r1 < M) H[((size_t)r1 * S_DIM + cc) >> 1] = __floats2half2_rn(o1.x, o1.y);
            } else {
                if (r0 < M) {
                    *(float2*)&C[(size_t)r0 * N + col] = o0;
                    if (Ch) *(__half2*)&Ch[(size_t)r0 * N + col] = __floats2half2_rn(o0.x, o0.y);
                }
                if (r1 < M) {
                    *(float2*)&C[(size_t)r1 * N + col] = o1;
                    if (Ch) *(__half2*)&Ch[(size_t)r1 * N + col] = __floats2half2_rn(o1.x, o1.y);
                }
            }
        }
    }
}

// ---------------- per-node aggregation, one warp/node, uint4 gathers, unroll x8 ----------------
// state[n] += sum_e relu(h2f(Psrc[src_e]) + h2f(Pdst[n]) + b); writes fp32 + fp16 state.
__global__ __launch_bounds__(256) void aggregate_kernel(const float* __restrict__ b_msg_r) {
    int warp = blockIdx.x * 8 + (threadIdx.x >> 5);
    if (warp >= N_NODES) return;
    int lane = threadIdx.x & 31;

    // base = Pdst[warp][lane*8 .. +7] (fp16) + b
    uint4 bq = __ldg((const uint4*)&g_Pdst[(size_t)warp * S_DIM + lane * 8]);
    float2 d0 = __half22float2(*(__half2*)&bq.x);
    float2 d1 = __half22float2(*(__half2*)&bq.y);
    float2 d2 = __half22float2(*(__half2*)&bq.z);
    float2 d3 = __half22float2(*(__half2*)&bq.w);
    const float4* Bb = (const float4*)b_msg_r;
    float4 bb0 = Bb[lane * 2 + 0];
    float4 bb1 = Bb[lane * 2 + 1];
    float4 base0 = make_float4(d0.x + bb0.x, d0.y + bb0.y, d1.x + bb0.z, d1.y + bb0.w);
    float4 base1 = make_float4(d2.x + bb1.x, d2.y + bb1.y, d3.x + bb1.z, d3.y + bb1.w);

    float4 acc0 = make_float4(0.f, 0.f, 0.f, 0.f);
    float4 acc1 = make_float4(0.f, 0.f, 0.f, 0.f);

    const uint4* Ph = (const uint4*)g_Psrc;   // row = 32 uint4
    int s = g_rowptr[warp];
    int e = g_rowptr[warp + 1];

#define ACC_EDGE(q)                                                          \
    do {                                                                     \
        float2 f0 = __half22float2(*(__half2*)&(q).x);                       \
        float2 f1 = __half22float2(*(__half2*)&(q).y);                       \
        float2 f2 = __half22float2(*(__half2*)&(q).z);                       \
        float2 f3 = __half22float2(*(__half2*)&(q).w);                       \
        acc0.x += fmaxf(f0.x + base0.x, 0.f);                                \
        acc0.y += fmaxf(f0.y + base0.y, 0.f);                                \
        acc0.z += fmaxf(f1.x + base0.z, 0.f);                                \
        acc0.w += fmaxf(f1.y + base0.w, 0.f);                                \
        acc1.x += fmaxf(f2.x + base1.x, 0.f);                                \
        acc1.y += fmaxf(f2.y + base1.y, 0.f);                                \
        acc1.z += fmaxf(f3.x + base1.z, 0.f);                                \
        acc1.w += fmaxf(f3.y + base1.w, 0.f);                                \
    } while (0)

    int i = s;
    for (; i + 8 <= e; i += 8) {
        int sx[8];
#pragma unroll
        for (int u = 0; u < 8; u++) sx[u] = __ldg(&g_esrc[i + u]);
        uint4 q[8];
#pragma unroll
        for (int u = 0; u < 8; u++) q[u] = __ldg(&Ph[(size_t)sx[u] * 32 + lane]);
#pragma unroll
        for (int u = 0; u < 8; u++) ACC_EDGE(q[u]);
    }
    if (i + 4 <= e) {
        int sx[4];
#pragma unroll
        for (int u = 0; u < 4; u++) sx[u] = __ldg(&g_esrc[i + u]);
        uint4 q[4];
#pragma unroll
        for (int u = 0; u < 4; u++) q[u] = __ldg(&Ph[(size_t)sx[u] * 32 + lane]);
#pragma unroll
        for (int u = 0; u < 4; u++) ACC_EDGE(q[u]);
        i += 4;
    }
    for (; i < e; i++) {
        int s0 = __ldg(&g_esrc[i]);
        uint4 q0 = __ldg(&Ph[(size_t)s0 * 32 + lane]);
        ACC_EDGE(q0);
    }
#undef ACC_EDGE

    float4* st = (float4*)&g_state[(size_t)warp * S_DIM + lane * 8];
    float4 s0 = st[0];
    float4 s1 = st[1];
    s0.x += acc0.x; s0.y += acc0.y; s0.z += acc0.z; s0.w += acc0.w;
    s1.x += acc1.x; s1.y += acc1.y; s1.z += acc1.z; s1.w += acc1.w;
    st[0] = s0;
    st[1] = s1;

    // fp16 shadow for the next GEMM
    __half2 h0 = __floats2half2_rn(s0.x, s0.y);
    __half2 h1 = __floats2half2_rn(s0.z, s0.w);
    __half2 h2 = __floats2half2_rn(s1.x, s1.y);
    __half2 h3 = __floats2half2_rn(s1.z, s1.w);
    uint4 pk;
    pk.x = *(unsigned*)&h0; pk.y = *(unsigned*)&h1;
    pk.z = *(unsigned*)&h2; pk.w = *(unsigned*)&h3;
    *(uint4*)&g_state_h[(size_t)warp * S_DIM + lane * 8] = pk;
}

// ---------------- launch ----------------
extern "C" void kernel_launch(void* const* d_in, const int* in_sizes, int n_in,
                              void* d_out, int out_size)
{
    const float* x        = (const float*)d_in[0];
    const int*   eidx     = (const int*)d_in[1];
    // d_in[2] = batch (unused by reference)
    const float* W_in     = (const float*)d_in[3];
    const float* b_in     = (const float*)d_in[4];
    const float* W_msg    = (const float*)d_in[5];   // [ROUNDS, 2S, S]
    const float* b_msg    = (const float*)d_in[6];   // [ROUNDS, S]
    const float* W_out    = (const float*)d_in[7];
    const float* b_out    = (const float*)d_in[8];
    float*       out      = (float*)d_out;

    float*  state;   cudaGetSymbolAddress((void**)&state,   g_state);
    __half* state_h; cudaGetSymbolAddress((void**)&state_h, g_state_h);
    __half* xh;      cudaGetSymbolAddress((void**)&xh,      g_xh);
    __half* Psrc;    cudaGetSymbolAddress((void**)&Psrc,    g_Psrc);
    __half* Pdst;    cudaGetSymbolAddress((void**)&Pdst,    g_Pdst);
    __half* WinT;    cudaGetSymbolAddress((void**)&WinT,    g_WinT);
    __half* WcatT;   cudaGetSymbolAddress((void**)&WcatT,   g_WcatT);
    __half* WoutT;   cudaGetSymbolAddress((void**)&WoutT,   g_WoutT);

    cudaFuncSetAttribute(gemm_f16_kernel,
                         cudaFuncAttributeMaxDynamicSharedMemorySize, SMEM_BYTES);

    // lazy host-side objects (stream/event creation is host-side, not device alloc)
    static cudaStream_t s_side = nullptr;
    static cudaEvent_t  ev_fork = nullptr, ev_join = nullptr;
    if (!s_side) {
        cudaStreamCreateWithFlags(&s_side, cudaStreamNonBlocking);
        cudaEventCreateWithFlags(&ev_fork, cudaEventDisableTiming);
        cudaEventCreateWithFlags(&ev_join, cudaEventDisableTiming);
    }

    // ---- fork: CSR chain on side stream, prep+input GEMM on main stream ----
    cudaEventRecord(ev_fork, 0);
    cudaStreamWaitEvent(s_side, ev_fork, 0);

    // side stream: CSR build (feeds only aggregate)
    zero_counts_kernel<<<(N_NODES + 255) / 256, 256, 0, s_side>>>();
    hist_kernel<<<(N_EDGES + 255) / 256, 256, 0, s_side>>>(eidx);
    scan_kernel<<<1, 1024, 0, s_side>>>();
    fill_kernel<<<(N_EDGES + 255) / 256, 256, 0, s_side>>>(eidx);
    cudaEventRecord(ev_join, s_side);

    // main stream: fp16 operand prep + input net
    {
        int tot = N_NODES * F_DIM + S_DIM * F_DIM
                + ROUNDS * 2 * S_DIM * S_DIM + L_DIM * S_DIM;
        prep_kernel<<<(tot + 255) / 256, 256>>>(x, W_in, W_msg, W_out);
    }
    {
        dim3 grid(S_DIM / TBN, (N_NODES + TBM - 1) / TBM);
        gemm_f16_kernel<<<grid, 256, SMEM_BYTES>>>(
            xh, WinT, b_in, state, state_h, nullptr, nullptr,
            N_NODES, S_DIM, F_DIM, 1);
    }

    // ---- message rounds; CSR join needed only before the first aggregate ----
    for (int r = 0; r < ROUNDS; r++) {
        {
            dim3 grid((2 * S_DIM) / TBN, (N_NODES + TBM - 1) / TBM);
            gemm_f16_kernel<<<grid, 256, SMEM_BYTES>>>(
                state_h, WcatT + (size_t)r * 2 * S_DIM * S_DIM, nullptr, nullptr,
                nullptr, Psrc, Pdst, N_NODES, 2 * S_DIM, S_DIM, 0);
        }
        if (r == 0) cudaStreamWaitEvent(0, ev_join, 0);   // join CSR before first gather
        aggregate_kernel<<<(N_NODES + 7) / 8, 256>>>(b_msg + (size_t)r * S_DIM);
    }

    // output net: out = state @ W_out + b_out
    {
        dim3 grid(1, (N_NODES + TBM - 1) / TBM);
        gemm_f16_kernel<<<grid, 256, SMEM_BYTES>>>(
            state_h, WoutT, b_out, out, nullptr, nullptr, nullptr,
            N_NODES, L_DIM, S_DIM, 0);
    }
}

// round 14
// speedup vs baseline: 1.2909x; 1.0359x over previous
#include <cuda_runtime.h>
#include <cuda_fp16.h>
#include <cstdint>

// Problem constants (match reference setup_inputs)
#define N_NODES 25000
#define N_EDGES 400000
#define F_DIM   128
#define S_DIM   256
#define L_DIM   64
#define ROUNDS  4

// ---------------- scratch (static __device__, no allocations) ----------------
__device__ __half g_state_h[N_NODES * S_DIM];               // fp16 state (accumulator + GEMM operand)
__device__ __half g_xh[N_NODES * F_DIM];
__device__ __half g_Psrc[N_NODES * S_DIM];                  // fp16 src-half of P
__device__ __half g_Pdst[N_NODES * S_DIM];                  // fp16 dst-half of P
__device__ __half g_WinT[S_DIM * F_DIM];                    // [N=256][K=128]
__device__ __half g_WcatT[ROUNDS * 2 * S_DIM * S_DIM];      // [r][N=512][K=256]
__device__ __half g_WoutT[L_DIM * S_DIM];                   // [N=64][K=256]
__device__ int    g_cnt[N_NODES];
__device__ int    g_cur[N_NODES];
__device__ int    g_rowptr[N_NODES + 1];
__device__ int    g_esrc[N_EDGES];

// ---------------- CSR build (counting sort by dest) ----------------
__global__ void zero_counts_kernel() {
    int i = blockIdx.x * blockDim.x + threadIdx.x;
    if (i < N_NODES) { g_cnt[i] = 0; g_cur[i] = 0; }
}

__global__ void hist_kernel(const int* __restrict__ edge_index) {
    int e = blockIdx.x * blockDim.x + threadIdx.x;
    if (e < N_EDGES) {
        int d = __ldg(&edge_index[N_EDGES + e]);
        atomicAdd(&g_cnt[d], 1);
    }
}

__global__ void scan_kernel() {
    __shared__ int warp_tot[32];
    const int CH = (N_NODES + 1023) / 1024;   // 25
    int t = threadIdx.x;
    int lane = t & 31, wid = t >> 5;
    int base = t * CH;
    int sum = 0;
#pragma unroll
    for (int i = 0; i < CH; i++) {
        int idx = base + i;
        if (idx < N_NODES) sum += g_cnt[idx];
    }
    int v = sum;
#pragma unroll
    for (int off = 1; off < 32; off <<= 1) {
        int n = __shfl_up_sync(0xffffffff, v, off);
        if (lane >= off) v += n;
    }
    if (lane == 31) warp_tot[wid] = v;
    __syncthreads();
    if (wid == 0) {
        int w = warp_tot[lane];
#pragma unroll
        for (int off = 1; off < 32; off <<= 1) {
            int n = __shfl_up_sync(0xffffffff, w, off);
            if (lane >= off) w += n;
        }
        warp_tot[lane] = w;
    }
    __syncthreads();
    int excl = v - sum + (wid > 0 ? warp_tot[wid - 1] : 0);
    int run = excl;
#pragma unroll
    for (int i = 0; i < CH; i++) {
        int idx = base + i;
        if (idx < N_NODES) { g_rowptr[idx] = run; run += g_cnt[idx]; }
    }
    if (t == 1023) g_rowptr[N_NODES] = run;
}

__global__ void fill_kernel(const int* __restrict__ edge_index) {
    int e = blockIdx.x * blockDim.x + threadIdx.x;
    if (e < N_EDGES) {
        int s = __ldg(&edge_index[e]);
        int d = __ldg(&edge_index[N_EDGES + e]);
        int pos = g_rowptr[d] + atomicAdd(&g_cur[d], 1);
        g_esrc[pos] = s;
    }
}

// ---------------- fp16 operand prep (x + all weights in one launch) ----------------
__global__ void prep_kernel(const float* __restrict__ x,
                            const float* __restrict__ W_in,
                            const float* __restrict__ W_msg,
                            const float* __restrict__ W_out) {
    const int NX = N_NODES * F_DIM;
    const int N1 = S_DIM * F_DIM;
    const int N2 = ROUNDS * 2 * S_DIM * S_DIM;
    const int N3 = L_DIM * S_DIM;
    int i = blockIdx.x * blockDim.x + threadIdx.x;
    if (i < NX) {
        g_xh[i] = __float2half(x[i]);
    } else if (i < NX + N1) {
        int t = i - NX;
        int j = t / F_DIM, k = t % F_DIM;
        g_WinT[t] = __float2half(W_in[k * S_DIM + j]);
    } else if (i < NX + N1 + N2) {
        int t = i - NX - N1;
        int r = t / (2 * S_DIM * S_DIM);
        int rem = t % (2 * S_DIM * S_DIM);
        int j = rem / S_DIM;       // 0..511
        int k = rem % S_DIM;
        const float* Wr = W_msg + (size_t)r * 2 * S_DIM * S_DIM;
        float v = (j < S_DIM) ? Wr[k * S_DIM + j] : Wr[(S_DIM + k) * S_DIM + (j - S_DIM)];
        g_WcatT[t] = __float2half(v);
    } else if (i < NX + N1 + N2 + N3) {
        int t = i - NX - N1 - N2;
        int j = t / S_DIM, k = t % S_DIM;
        g_WoutT[t] = __float2half(W_out[k * L_DIM + j]);
    }
}

// ---------------- fp16 tensor-core GEMM: cp.async 3-stage + ldmatrix frags ----------------
// C[M,N] = act(A[M,K] @ B^T + bias), B given as [N][K] fp16 (pre-transposed).
// BM=128, BN=128, BK=32, 256 threads (8 warps), warp tile 64x32 via m16n8k16.
#define TBM 128
#define TBN 128
#define TBK 32
#define KP  56
#define NSTAGE 3
#define TILE_ELEMS (128 * KP)
#define SMEM_BYTES (NSTAGE * 2 * TILE_ELEMS * 2)

__device__ __forceinline__ void cp_async16(unsigned int dst, const void* src, int nbytes) {
    asm volatile("cp.async.ca.shared.global [%0], [%1], 16, %2;\n"
                 :: "r"(dst), "l"(src), "r"(nbytes));
}
__device__ __forceinline__ void cp_async_commit() {
    asm volatile("cp.async.commit_group;\n");
}
template <int N>
__device__ __forceinline__ void cp_async_wait() {
    asm volatile("cp.async.wait_group %0;\n" :: "n"(N));
}
__device__ __forceinline__ void ldsm_x4(unsigned& r0, unsigned& r1, unsigned& r2, unsigned& r3,
                                        unsigned int addr) {
    asm volatile("ldmatrix.sync.aligned.m8n8.x4.shared.b16 {%0,%1,%2,%3}, [%4];"
                 : "=r"(r0), "=r"(r1), "=r"(r2), "=r"(r3) : "r"(addr));
}

__global__ __launch_bounds__(256, 2) void gemm_f16_kernel(
    const __half* __restrict__ A, const __half* __restrict__ B,
    const float* __restrict__ bias, float* __restrict__ C,
    __half* __restrict__ Ch, __half* __restrict__ Csrc, __half* __restrict__ Cdst,
    int M, int N, int K, int do_relu)
{
    extern __shared__ __half sm[];
    __half* As = sm;                               // [NSTAGE][128][KP]
    __half* Bs = sm + NSTAGE * TILE_ELEMS;         // [NSTAGE][128][KP]

    int tid  = threadIdx.x;
    int lane = tid & 31;
    int wid  = tid >> 5;
    int warp_m = wid & 1;
    int warp_n = wid >> 1;
    int m_warp = warp_m * 64;
    int n_warp = warp_n * 32;
    int g   = lane >> 2;
    int tig = lane & 3;

    int row_blk = blockIdx.y * TBM;
    int col_blk = blockIdx.x * TBN;

    float c[4][4][4];
#pragma unroll
    for (int mt = 0; mt < 4; mt++)
#pragma unroll
        for (int nt = 0; nt < 4; nt++)
#pragma unroll
            for (int i = 0; i < 4; i++) c[mt][nt][i] = 0.f;

    int kt   = tid & 3;
    int trow = tid >> 2;

    unsigned int As_u32 = (unsigned int)__cvta_generic_to_shared(As);
    unsigned int Bs_u32 = (unsigned int)__cvta_generic_to_shared(Bs);

    int a_row_off = (lane & 7) + ((lane >> 3) & 1) * 8;
    int a_kk_off  = (lane >> 4) * 8;
    int b_row_off = (lane & 7) + (lane >> 4) * 8;
    int b_kk_off  = ((lane >> 3) & 1) * 8;

    int nk = K / TBK;

    auto issue_tile = [&](int t, int s) {
        int k0 = t * TBK;
#pragma unroll
        for (int p = 0; p < 2; p++) {
            int row = p * 64 + trow;
            unsigned int dA = As_u32 + (unsigned int)(s * TILE_ELEMS + row * KP + kt * 8) * 2u;
            int ar = row_blk + row;
            cp_async16(dA, &A[(size_t)ar * K + k0 + kt * 8], (ar < M) ? 16 : 0);
            unsigned int dB = Bs_u32 + (unsigned int)(s * TILE_ELEMS + row * KP + kt * 8) * 2u;
            int br = col_blk + row;
            cp_async16(dB, &B[(size_t)br * K + k0 + kt * 8], (br < N) ? 16 : 0);
        }
        cp_async_commit();
    };

    issue_tile(0, 0);
    if (nk > 1) issue_tile(1, 1);
    else cp_async_commit();

    for (int t = 0; t < nk; t++) {
        cp_async_wait<1>();
        __syncthreads();

        int cur = t % NSTAGE;
        unsigned int Ac_u32 = As_u32 + (unsigned int)(cur * TILE_ELEMS) * 2u;
        unsigned int Bc_u32 = Bs_u32 + (unsigned int)(cur * TILE_ELEMS) * 2u;

        if (t + 2 < nk) issue_tile(t + 2, (t + 2) % NSTAGE);
        else cp_async_commit();

#pragma unroll
        for (int ks = 0; ks < TBK; ks += 16) {
            unsigned af[4][4], bf[4][2];
#pragma unroll
            for (int mt = 0; mt < 4; mt++) {
                int mb = m_warp + mt * 16;
                unsigned int aaddr = Ac_u32
                    + (unsigned int)((mb + a_row_off) * KP + ks + a_kk_off) * 2u;
                ldsm_x4(af[mt][0], af[mt][1], af[mt][2], af[mt][3], aaddr);
            }
#pragma unroll
            for (int ntp = 0; ntp < 2; ntp++) {
                int nb = n_warp + ntp * 16;
                unsigned int baddr = Bc_u32
                    + (unsigned int)((nb + b_row_off) * KP + ks + b_kk_off) * 2u;
                ldsm_x4(bf[ntp * 2][0], bf[ntp * 2][1],
                        bf[ntp * 2 + 1][0], bf[ntp * 2 + 1][1], baddr);
            }
#pragma unroll
            for (int mt = 0; mt < 4; mt++)
#pragma unroll
                for (int nt = 0; nt < 4; nt++) {
                    asm volatile(
                        "mma.sync.aligned.m16n8k16.row.col.f32.f16.f16.f32 "
                        "{%0,%1,%2,%3}, {%4,%5,%6,%7}, {%8,%9}, {%0,%1,%2,%3};"
                        : "+f"(c[mt][nt][0]), "+f"(c[mt][nt][1]),
                          "+f"(c[mt][nt][2]), "+f"(c[mt][nt][3])
                        : "r"(af[mt][0]), "r"(af[mt][1]), "r"(af[mt][2]), "r"(af[mt][3]),
                          "r"(bf[nt][0]), "r"(bf[nt][1]));
                }
        }
        __syncthreads();
    }

    // epilogue
#pragma unroll
    for (int mt = 0; mt < 4; mt++) {
#pragma unroll
        for (int nt = 0; nt < 4; nt++) {
            int col = col_blk + n_warp + nt * 8 + tig * 2;
            if (col >= N) continue;
            float bv0 = bias ? bias[col] : 0.f;
            float bv1 = bias ? bias[col + 1] : 0.f;
            int r0 = row_blk + m_warp + mt * 16 + g;
            int r1 = r0 + 8;
            float2 o0, o1;
            o0.x = c[mt][nt][0] + bv0; o0.y = c[mt][nt][1] + bv1;
            o1.x = c[mt][nt][2] + bv0; o1.y = c[mt][nt][3] + bv1;
            if (do_relu) {
                o0.x = fmaxf(o0.x, 0.f); o0.y = fmaxf(o0.y, 0.f);
                o1.x = fmaxf(o1.x, 0.f); o1.y = fmaxf(o1.y, 0.f);
            }
            if (Csrc) {
                // split mode: cols [0,S) -> fp16 Psrc, cols [S,2S) -> fp16 Pdst
                __half2* H = (col < S_DIM) ? (__half2*)Csrc : (__half2*)Cdst;
                int cc = (col < S_DIM) ? col : col - S_DIM;
                if (r0 < M) H[((size_t)r0 * S_DIM + cc) >> 1] = __floats2half2_rn(o0.x, o0.y);
                if (r1 < M) H[((size_t)r1 * S_DIM + cc) >> 1] = __floats2half2_rn(o1.x, o1.y);
            } else {
                if (r0 < M) {
                    if (C)  *(float2*)&C[(size_t)r0 * N + col] = o0;
                    if (Ch) *(__half2*)&Ch[(size_t)r0 * N + col] = __floats2half2_rn(o0.x, o0.y);
                }
                if (r1 < M) {
                    if (C)  *(float2*)&C[(size_t)r1 * N + col] = o1;
                    if (Ch) *(__half2*)&Ch[(size_t)r1 * N + col] = __floats2half2_rn(o1.x, o1.y);
                }
            }
        }
    }
}

// ---------------- per-node aggregation, one warp/node, uint4 gathers, unroll x8 ----------------
// state_h[n] = fp16( h2f(state_h[n]) + sum_e relu(h2f(Psrc[src_e]) + h2f(Pdst[n]) + b) )
__global__ __launch_bounds__(256) void aggregate_kernel(const float* __restrict__ b_msg_r) {
    int warp = blockIdx.x * 8 + (threadIdx.x >> 5);
    if (warp >= N_NODES) return;
    int lane = threadIdx.x & 31;

    // base = Pdst[warp][lane*8 .. +7] (fp16) + b
    uint4 bq = __ldg((const uint4*)&g_Pdst[(size_t)warp * S_DIM + lane * 8]);
    float2 d0 = __half22float2(*(__half2*)&bq.x);
    float2 d1 = __half22float2(*(__half2*)&bq.y);
    float2 d2 = __half22float2(*(__half2*)&bq.z);
    float2 d3 = __half22float2(*(__half2*)&bq.w);
    const float4* Bb = (const float4*)b_msg_r;
    float4 bb0 = Bb[lane * 2 + 0];
    float4 bb1 = Bb[lane * 2 + 1];
    float4 base0 = make_float4(d0.x + bb0.x, d0.y + bb0.y, d1.x + bb0.z, d1.y + bb0.w);
    float4 base1 = make_float4(d2.x + bb1.x, d2.y + bb1.y, d3.x + bb1.z, d3.y + bb1.w);

    float4 acc0 = make_float4(0.f, 0.f, 0.f, 0.f);
    float4 acc1 = make_float4(0.f, 0.f, 0.f, 0.f);

    const uint4* Ph = (const uint4*)g_Psrc;   // row = 32 uint4
    int s = g_rowptr[warp];
    int e = g_rowptr[warp + 1];

#define ACC_EDGE(q)                                                          \
    do {                                                                     \
        float2 f0 = __half22float2(*(__half2*)&(q).x);                       \
        float2 f1 = __half22float2(*(__half2*)&(q).y);                       \
        float2 f2 = __half22float2(*(__half2*)&(q).z);                       \
        float2 f3 = __half22float2(*(__half2*)&(q).w);                       \
        acc0.x += fmaxf(f0.x + base0.x, 0.f);                                \
        acc0.y += fmaxf(f0.y + base0.y, 0.f);                                \
        acc0.z += fmaxf(f1.x + base0.z, 0.f);                                \
        acc0.w += fmaxf(f1.y + base0.w, 0.f);                                \
        acc1.x += fmaxf(f2.x + base1.x, 0.f);                                \
        acc1.y += fmaxf(f2.y + base1.y, 0.f);                                \
        acc1.z += fmaxf(f3.x + base1.z, 0.f);                                \
        acc1.w += fmaxf(f3.y + base1.w, 0.f);                                \
    } while (0)

    int i = s;
    for (; i + 8 <= e; i += 8) {
        int sx[8];
#pragma unroll
        for (int u = 0; u < 8; u++) sx[u] = __ldg(&g_esrc[i + u]);
        uint4 q[8];
#pragma unroll
        for (int u = 0; u < 8; u++) q[u] = __ldg(&Ph[(size_t)sx[u] * 32 + lane]);
#pragma unroll
        for (int u = 0; u < 8; u++) ACC_EDGE(q[u]);
    }
    if (i + 4 <= e) {
        int sx[4];
#pragma unroll
        for (int u = 0; u < 4; u++) sx[u] = __ldg(&g_esrc[i + u]);
        uint4 q[4];
#pragma unroll
        for (int u = 0; u < 4; u++) q[u] = __ldg(&Ph[(size_t)sx[u] * 32 + lane]);
#pragma unroll
        for (int u = 0; u < 4; u++) ACC_EDGE(q[u]);
        i += 4;
    }
    for (; i < e; i++) {
        int s0 = __ldg(&g_esrc[i]);
        uint4 q0 = __ldg(&Ph[(size_t)s0 * 32 + lane]);
        ACC_EDGE(q0);
    }
#undef ACC_EDGE

    // fp16 state accumulate: s' = fp16(h2f(s) + acc)
    uint4* stp = (uint4*)&g_state_h[(size_t)warp * S_DIM + lane * 8];
    uint4 sq = *stp;
    float2 s0 = __half22float2(*(__half2*)&sq.x);
    float2 s1 = __half22float2(*(__half2*)&sq.y);
    float2 s2 = __half22float2(*(__half2*)&sq.z);
    float2 s3 = __half22float2(*(__half2*)&sq.w);
    __half2 h0 = __floats2half2_rn(s0.x + acc0.x, s0.y + acc0.y);
    __half2 h1 = __floats2half2_rn(s1.x + acc0.z, s1.y + acc0.w);
    __half2 h2 = __floats2half2_rn(s2.x + acc1.x, s2.y + acc1.y);
    __half2 h3 = __floats2half2_rn(s3.x + acc1.z, s3.y + acc1.w);
    uint4 pk;
    pk.x = *(unsigned*)&h0; pk.y = *(unsigned*)&h1;
    pk.z = *(unsigned*)&h2; pk.w = *(unsigned*)&h3;
    *stp = pk;
}

// ---------------- launch ----------------
extern "C" void kernel_launch(void* const* d_in, const int* in_sizes, int n_in,
                              void* d_out, int out_size)
{
    const float* x        = (const float*)d_in[0];
    const int*   eidx     = (const int*)d_in[1];
    // d_in[2] = batch (unused by reference)
    const float* W_in     = (const float*)d_in[3];
    const float* b_in     = (const float*)d_in[4];
    const float* W_msg    = (const float*)d_in[5];   // [ROUNDS, 2S, S]
    const float* b_msg    = (const float*)d_in[6];   // [ROUNDS, S]
    const float* W_out    = (const float*)d_in[7];
    const float* b_out    = (const float*)d_in[8];
    float*       out      = (float*)d_out;

    __half* state_h; cudaGetSymbolAddress((void**)&state_h, g_state_h);
    __half* xh;      cudaGetSymbolAddress((void**)&xh,      g_xh);
    __half* Psrc;    cudaGetSymbolAddress((void**)&Psrc,    g_Psrc);
    __half* Pdst;    cudaGetSymbolAddress((void**)&Pdst,    g_Pdst);
    __half* WinT;    cudaGetSymbolAddress((void**)&WinT,    g_WinT);
    __half* WcatT;   cudaGetSymbolAddress((void**)&WcatT,   g_WcatT);
    __half* WoutT;   cudaGetSymbolAddress((void**)&WoutT,   g_WoutT);

    cudaFuncSetAttribute(gemm_f16_kernel,
                         cudaFuncAttributeMaxDynamicSharedMemorySize, SMEM_BYTES);

    // lazy host-side objects (stream/event creation is host-side, not device alloc)
    static cudaStream_t s_side = nullptr;
    static cudaEvent_t  ev_fork = nullptr, ev_join = nullptr;
    if (!s_side) {
        cudaStreamCreateWithFlags(&s_side, cudaStreamNonBlocking);
        cudaEventCreateWithFlags(&ev_fork, cudaEventDisableTiming);
        cudaEventCreateWithFlags(&ev_join, cudaEventDisableTiming);
    }

    // ---- fork: CSR chain on side stream, prep+input GEMM on main stream ----
    cudaEventRecord(ev_fork, 0);
    cudaStreamWaitEvent(s_side, ev_fork, 0);

    zero_counts_kernel<<<(N_NODES + 255) / 256, 256, 0, s_side>>>();
    hist_kernel<<<(N_EDGES + 255) / 256, 256, 0, s_side>>>(eidx);
    scan_kernel<<<1, 1024, 0, s_side>>>();
    fill_kernel<<<(N_EDGES + 255) / 256, 256, 0, s_side>>>(eidx);
    cudaEventRecord(ev_join, s_side);

    // main stream: fp16 operand prep + input net (fp16 state only)
    {
        int tot = N_NODES * F_DIM + S_DIM * F_DIM
                + ROUNDS * 2 * S_DIM * S_DIM + L_DIM * S_DIM;
        prep_kernel<<<(tot + 255) / 256, 256>>>(x, W_in, W_msg, W_out);
    }
    {
        dim3 grid(S_DIM / TBN, (N_NODES + TBM - 1) / TBM);
        gemm_f16_kernel<<<grid, 256, SMEM_BYTES>>>(
            xh, WinT, b_in, nullptr, state_h, nullptr, nullptr,
            N_NODES, S_DIM, F_DIM, 1);
    }

    // ---- message rounds; CSR join needed only before the first aggregate ----
    for (int r = 0; r < ROUNDS; r++) {
        {
            dim3 grid((2 * S_DIM) / TBN, (N_NODES + TBM - 1) / TBM);
            gemm_f16_kernel<<<grid, 256, SMEM_BYTES>>>(
                state_h, WcatT + (size_t)r * 2 * S_DIM * S_DIM, nullptr, nullptr,
                nullptr, Psrc, Pdst, N_NODES, 2 * S_DIM, S_DIM, 0);
        }
        if (r == 0) cudaStreamWaitEvent(0, ev_join, 0);   // join CSR before first gather
        aggregate_kernel<<<(N_NODES + 7) / 8, 256>>>(b_msg + (size_t)r * S_DIM);
    }

    // output net: out = state @ W_out + b_out (fp32 output)
    {
        dim3 grid(1, (N_NODES + TBM - 1) / TBM);
        gemm_f16_kernel<<<grid, 256, SMEM_BYTES>>>(
            state_h, WoutT, b_out, out, nullptr, nullptr, nullptr,
            N_NODES, L_DIM, S_DIM, 0);
    }
}